// round 7
// baseline (speedup 1.0000x reference)
#include <cuda_runtime.h>

#define NCONF   8
#define NATOMS  10
#define NSTATES 4
#define NBASIS  24
#define HIDDEN  48
#define NTYPES  4
#define PPC     90            // ordered pairs, contiguous: p = i*9 + (j - (j>i))
#define NT      256
#define NBLOCKS (NCONF*NATOMS)

#define PI_F 3.14159265358979323846f
#define CUT  6.0f
#define KARG (PI_F/CUT)
#define AL   1.5f
#define DLT  (CUT/23.0f)
#define FULLM 0xffffffffu

// cross-block scratch (no cudaMalloc allowed)
__device__ float g_kin[NCONF*NATOMS*NSTATES];
__device__ float g_T[NCONF*NSTATES];
__device__ int   g_fin;

__device__ __forceinline__ int jlA(int t, int A) { return t + (t >= A); }

__device__ __forceinline__ float fast_tanh(float u) {
    float ex = __expf(2.f*u);
    return 1.f - __fdividef(2.f, ex + 1.f);
}

__global__ void __launch_bounds__(NT, 1)
fused_kernel(const float* __restrict__ pot, const float* __restrict__ cart,
             const int* __restrict__ species, const float* __restrict__ massrev,
             const float* __restrict__ W1, const float* __restrict__ B1,
             const float* __restrict__ W2, const float* __restrict__ Emb,
             const float* __restrict__ elevel, float* __restrict__ out)
{
    __shared__ __align__(16) float W1s[NBASIS][52];
    __shared__ __align__(16) float W2s[HIDDEN][4];
    __shared__ float B1all[NTYPES][48];
    __shared__ float EmbAll[NTYPES][4];
    __shared__ int   s_sp[NATOMS];
    __shared__ float s_cart[NATOMS*3];
    __shared__ float s_pe, s_mass, s_el[4];
    __shared__ float G0[PPC][25];
    __shared__ float radv[PPC];
    __shared__ float G1k[18][25], G2k[18][25];
    __shared__ float rad1k[18], rad2k[18];
    __shared__ float wdd[3][18], wdh[3][18];
    __shared__ float densv[NATOMS][25];
    __shared__ float Rr[NATOMS];
    __shared__ float tval[NATOMS][49], f1a[NATOMS][49], f2a[NATOMS][49];
    __shared__ __align__(16) float U1[18][52], U2[18][52];
    __shared__ float pv[NATOMS][4];
    __shared__ float V1[18][4], V2[18][4], Qn[9][4];
    __shared__ float QA[3][4];
    __shared__ float wpd[3][NATOMS][4], wph[3][NATOMS][4];
    __shared__ float Tval[4];
    __shared__ float Bsh[3][4], Hsh[3][4];

    const int tid = threadIdx.x;
    const int c   = blockIdx.x / NATOMS;
    const int A   = blockIdx.x % NATOMS;

    // -------- P1: all global loads up front, no dependent chains --------
    for (int i = tid; i < NBASIS*HIDDEN; i += NT)
        W1s[i / HIDDEN][i % HIDDEN] = W1[i];
    if (tid < HIDDEN*NSTATES) {
        W2s[tid >> 2][tid & 3] = W2[tid];
        B1all[tid / 48][tid % 48] = B1[tid];        // all 4 species rows
    } else if (tid < 192 + NTYPES*NSTATES) {
        int i = tid - 192;
        EmbAll[i >> 2][i & 3] = Emb[i];
    } else if (tid < 208 + NATOMS) {
        s_sp[tid - 208] = species[c*NATOMS + (tid - 208)];
    } else if (tid >= 218 && tid < 218 + NATOMS*3) {
        s_cart[tid - 218] = cart[c*NATOMS*3 + (tid - 218)];
    } else if (tid == 248) {
        s_mass = massrev[c*NATOMS + A];
    } else if (tid == 249) {
        s_pe = pot[c] - pot[NCONF-1];
    } else if (tid >= 250 && tid < 250 + NSTATES) {
        s_el[tid - 250] = elevel[tid - 250];
    }
    __syncthreads();

    // -------- P2: pair geometry, branch-free; A-pair jets on separate warps --------
    if (tid < PPC) {
        const int p = tid;
        const int i = p / 9, jr = p % 9;
        const int j = jr + (jr >= i);
        float dx = s_cart[j*3+0] - s_cart[i*3+0];
        float dy = s_cart[j*3+1] - s_cart[i*3+1];
        float dz = s_cart[j*3+2] - s_cart[i*3+2];
        float d2 = fmaf(dx, dx, fmaf(dy, dy, dz*dz));
        float d  = sqrtf(d2);
        float arg = d * KARG;
        float sn = __sinf(arg), cs = __cosf(arg);
        radv[p] = sn*sn*sn;
        float f0 = (d < CUT) ? 0.5f*(cs + 1.f) : 0.f;

        // rbf via 4 independent 6-step recurrences (depth 12 mults)
        const float gg = __expf(-2.f*AL*DLT*DLT);
        float gg2 = gg*gg, gg3 = gg2*gg, gg6 = gg3*gg3;
        float tc = __expf(fmaf(2.f*AL*DLT, d, -AL*DLT*DLT));
        float t0 = tc, t1 = tc*gg6, t2 = t1*gg6, t3 = t2*gg6;
        float rb0  = __expf(-AL*d2);
        float d6   = d -  6.f*DLT; float rb6  = __expf(-AL*d6*d6);
        float d12  = d - 12.f*DLT; float rb12 = __expf(-AL*d12*d12);
        float d18  = d - 18.f*DLT; float rb18 = __expf(-AL*d18*d18);
        #pragma unroll
        for (int i2 = 0; i2 < 6; i2++) {
            G0[p][i2]      = rb0 *f0;
            G0[p][6 + i2]  = rb6 *f0;
            G0[p][12 + i2] = rb12*f0;
            G0[p][18 + i2] = rb18*f0;
            rb0 *= t0; rb6 *= t1; rb12 *= t2; rb18 *= t3;
            t0 *= gg; t1 *= gg; t2 *= gg; t3 *= gg;
        }
    } else if (tid >= 96 && tid < 96 + 18) {
        // A-pair jets: k<9 -> center A (i=A, j=jlA(k)); k>=9 -> neighbor A
        const int k   = tid - 96;
        const bool isC = (k < 9);
        const int i = isC ? A : jlA(k - 9, A);
        const int j = isC ? jlA(k, A) : A;
        float dx = s_cart[j*3+0] - s_cart[i*3+0];
        float dy = s_cart[j*3+1] - s_cart[i*3+1];
        float dz = s_cart[j*3+2] - s_cart[i*3+2];
        float d2 = fmaf(dx, dx, fmaf(dy, dy, dz*dz));
        float d  = sqrtf(d2);
        float arg = d * KARG;
        float sn = __sinf(arg), cs = __cosf(arg);
        float f0, fd1, fd2;
        if (d < CUT) {
            f0  = 0.5f*(cs + 1.f);
            fd1 = -0.5f*KARG*sn;
            fd2 = -0.5f*KARG*KARG*cs;
        } else { f0 = 0.f; fd1 = 0.f; fd2 = 0.f; }
        rad1k[k] = 3.f*sn*sn*cs * KARG;
        rad2k[k] = (6.f*sn*cs*cs - 3.f*sn*sn*sn) * (KARG*KARG);
        float invd = __frcp_rn(d);
        float sgn = isC ? -1.f : 1.f;
        float ex = dx*invd, ey = dy*invd, ez = dz*invd;
        wdd[0][k] = sgn*ex; wdh[0][k] = (1.f - ex*ex)*invd;
        wdd[1][k] = sgn*ey; wdh[1][k] = (1.f - ey*ey)*invd;
        wdd[2][k] = sgn*ez; wdh[2][k] = (1.f - ez*ez)*invd;

        const float gg = __expf(-2.f*AL*DLT*DLT);
        float gg2 = gg*gg, gg3 = gg2*gg, gg6 = gg3*gg3;
        float tc = __expf(fmaf(2.f*AL*DLT, d, -AL*DLT*DLT));
        float t0 = tc, t1 = tc*gg6, t2 = t1*gg6, t3 = t2*gg6;
        float rb0  = __expf(-AL*d2);
        float dd6  = d -  6.f*DLT; float rb6  = __expf(-AL*dd6*dd6);
        float dd12 = d - 12.f*DLT; float rb12 = __expf(-AL*dd12*dd12);
        float dd18 = d - 18.f*DLT; float rb18 = __expf(-AL*dd18*dd18);
        #pragma unroll
        for (int i2 = 0; i2 < 6; i2++) {
            #pragma unroll
            for (int sub = 0; sub < 4; sub++) {
                int b = sub*6 + i2;
                float rb = (sub==0) ? rb0 : (sub==1) ? rb6 : (sub==2) ? rb12 : rb18;
                float t  = d - (float)b*DLT;
                float r1 = -2.f*AL*t*rb;
                float r2 = (4.f*AL*AL*t*t - 2.f*AL)*rb;
                G1k[k][b] = r1*f0 + rb*fd1;
                G2k[k][b] = r2*f0 + 2.f*r1*fd1 + rb*fd2;
            }
            rb0 *= t0; rb6 *= t1; rb12 *= t2; rb18 *= t3;
            t0 *= gg; t1 *= gg; t2 *= gg; t3 *= gg;
        }
    }
    __syncthreads();

    // -------- P3: densv, Rr, U1/U2 --------
    for (int it = tid; it < NATOMS*NBASIS + NATOMS; it += NT) {
        if (it < NATOMS*NBASIS) {
            int at = it / NBASIS, b = it % NBASIS;
            float a0 = 0.f, a1 = 0.f;
            #pragma unroll
            for (int r = 0; r < 8; r += 2) {
                a0 += G0[at*9 + r][b];
                a1 += G0[at*9 + r + 1][b];
            }
            densv[at][b] = a0 + a1 + G0[at*9 + 8][b];
        } else {
            int at = it - NATOMS*NBASIS;
            float r = 0.f;
            #pragma unroll
            for (int j = 0; j < NATOMS; j++)
                if (j != at) r += radv[j*9 + (at - (at > j))];
            Rr[at] = r;
        }
    }
    if (tid < 18*12) {   // U1/U2, hh quad-blocked, 8 independent chains
        int k = tid / 12, hq = (tid % 12) * 4;
        float a0=0,a1=0,a2=0,a3=0,b0=0,b1=0,b2=0,b3=0;
        #pragma unroll
        for (int b = 0; b < NBASIS; b++) {
            float g1 = G1k[k][b], g2 = G2k[k][b];
            float4 w = *(const float4*)&W1s[b][hq];
            a0 = fmaf(g1, w.x, a0); a1 = fmaf(g1, w.y, a1);
            a2 = fmaf(g1, w.z, a2); a3 = fmaf(g1, w.w, a3);
            b0 = fmaf(g2, w.x, b0); b1 = fmaf(g2, w.y, b1);
            b2 = fmaf(g2, w.z, b2); b3 = fmaf(g2, w.w, b3);
        }
        U1[k][hq]=a0; U1[k][hq+1]=a1; U1[k][hq+2]=a2; U1[k][hq+3]=a3;
        U2[k][hq]=b0; U2[k][hq+1]=b1; U2[k][hq+2]=b2; U2[k][hq+3]=b3;
    }
    __syncthreads();

    // -------- P4: tanh value path (4-way split accumulation) --------
    for (int it = tid; it < NATOMS*HIDDEN; it += NT) {
        int at = it / HIDDEN, hh = it % HIDDEN;
        float u0 = B1all[s_sp[at]][hh], u1 = 0.f, u2 = 0.f, u3 = 0.f;
        #pragma unroll
        for (int b = 0; b < NBASIS; b += 4) {
            u0 = fmaf(densv[at][b  ], W1s[b  ][hh], u0);
            u1 = fmaf(densv[at][b+1], W1s[b+1][hh], u1);
            u2 = fmaf(densv[at][b+2], W1s[b+2][hh], u2);
            u3 = fmaf(densv[at][b+3], W1s[b+3][hh], u3);
        }
        float t  = fast_tanh((u0 + u1) + (u2 + u3));
        float f1 = 1.f - t*t;
        tval[at][hh] = t;
        f1a[at][hh]  = f1;
        f2a[at][hh]  = -2.f*t*f1;
    }
    __syncthreads();

    // -------- P5: pv, V1/V2, Qn + QA cross-term (warps 5-7) --------
    const int w    = tid >> 5;
    const int lane = tid & 31;
    if (tid < NATOMS*NSTATES) {
        int at = tid >> 2, s = tid & 3;
        float a0 = EmbAll[s_sp[at]][s], a1 = 0.f;
        #pragma unroll
        for (int hh = 0; hh < HIDDEN; hh += 2) {
            a0 = fmaf(tval[at][hh  ], W2s[hh  ][s], a0);
            a1 = fmaf(tval[at][hh+1], W2s[hh+1][s], a1);
        }
        pv[at][s] = a0 + a1;
    } else if (tid >= 64 && tid < 64 + 36) {
        int idx = tid - 64;
        int k = idx >> 1, which = idx & 1;
        int cen = (k < 9) ? A : jlA(k - 9, A);
        float v0=0,v1=0,v2=0,v3=0, w0=0,w1=0,w2=0,w3=0;
        #pragma unroll
        for (int hh = 0; hh < HIDDEN; hh += 2) {
            float ua = (which ? U2[k][hh  ] : U1[k][hh  ]) * f1a[cen][hh  ];
            float ub = (which ? U2[k][hh+1] : U1[k][hh+1]) * f1a[cen][hh+1];
            float4 wa = *(const float4*)&W2s[hh  ][0];
            float4 wb = *(const float4*)&W2s[hh+1][0];
            v0 = fmaf(ua, wa.x, v0); v1 = fmaf(ua, wa.y, v1);
            v2 = fmaf(ua, wa.z, v2); v3 = fmaf(ua, wa.w, v3);
            w0 = fmaf(ub, wb.x, w0); w1 = fmaf(ub, wb.y, w1);
            w2 = fmaf(ub, wb.z, w2); w3 = fmaf(ub, wb.w, w3);
        }
        if (which) { V2[k][0]=v0+w0; V2[k][1]=v1+w1; V2[k][2]=v2+w2; V2[k][3]=v3+w3; }
        else       { V1[k][0]=v0+w0; V1[k][1]=v1+w1; V1[k][2]=v2+w2; V1[k][3]=v3+w3; }
    } else if (tid >= 128 && tid < 128 + 9) {
        int k9 = tid - 128;
        int cen = jlA(k9, A);
        float q0=0,q1=0,q2=0,q3=0, r0=0,r1=0,r2=0,r3=0;
        #pragma unroll
        for (int hh = 0; hh < HIDDEN; hh += 2) {
            float ua = U1[9+k9][hh  ];
            float ub = U1[9+k9][hh+1];
            float ca = f2a[cen][hh  ] * ua * ua;
            float cb = f2a[cen][hh+1] * ub * ub;
            float4 wa = *(const float4*)&W2s[hh  ][0];
            float4 wb = *(const float4*)&W2s[hh+1][0];
            q0 = fmaf(ca, wa.x, q0); q1 = fmaf(ca, wa.y, q1);
            q2 = fmaf(ca, wa.z, q2); q3 = fmaf(ca, wa.w, q3);
            r0 = fmaf(cb, wb.x, r0); r1 = fmaf(cb, wb.y, r1);
            r2 = fmaf(cb, wb.z, r2); r3 = fmaf(cb, wb.w, r3);
        }
        Qn[k9][0]=q0+r0; Qn[k9][1]=q1+r1; Qn[k9][2]=q2+r2; Qn[k9][3]=q3+r3;
    } else if (w >= 5) {
        const int mu = w - 5;   // warps 5,6,7 -> mu 0,1,2
        float q0=0,q1=0,q2=0,q3=0;
        #pragma unroll
        for (int rep = 0; rep < 2; rep++) {
            int hh = lane + rep*32;
            if (hh < HIDDEN) {
                float ud = 0.f;
                #pragma unroll
                for (int k = 0; k < 9; k++)
                    ud = fmaf(wdd[mu][k], U1[k][hh], ud);
                float cf = f2a[A][hh] * ud * ud;
                float4 wv = *(const float4*)&W2s[hh][0];
                q0 = fmaf(cf, wv.x, q0); q1 = fmaf(cf, wv.y, q1);
                q2 = fmaf(cf, wv.z, q2); q3 = fmaf(cf, wv.w, q3);
            }
        }
        #pragma unroll
        for (int off = 16; off > 0; off >>= 1) {
            q0 += __shfl_xor_sync(FULLM, q0, off);
            q1 += __shfl_xor_sync(FULLM, q1, off);
            q2 += __shfl_xor_sync(FULLM, q2, off);
            q3 += __shfl_xor_sync(FULLM, q3, off);
        }
        if (lane == 0) { QA[mu][0]=q0; QA[mu][1]=q1; QA[mu][2]=q2; QA[mu][3]=q3; }
    }
    __syncthreads();

    // -------- P6: directions (warps 0-2) + Tval (warp 3) --------
    if (tid >= 96 && tid < 96 + NSTATES) {
        int s = tid - 96;
        float acc = 0.f;
        #pragma unroll
        for (int j = 0; j < NATOMS; j++)
            acc = fmaf(pv[j][s], Rr[j], acc);
        Tval[s] = acc;
    }
    if (w < 3) {
        const int mu = w;
        float accA = 0.f;
        if (lane < 8) {
            int s = lane & 3;
            bool second = lane >= 4;
            #pragma unroll
            for (int k = 0; k < 9; k++) {
                float dd = wdd[mu][k], dh = wdh[mu][k];
                accA += second ? fmaf(dd*dd, V2[k][s], dh*V1[k][s])
                               : dd*V1[k][s];
            }
        }
        if (lane < 4)      wpd[mu][A][lane]   = accA;
        else if (lane < 8) wph[mu][A][lane-4] = accA + QA[mu][lane-4];
        __syncwarp();

        #pragma unroll
        for (int base = 0; base < 36; base += 32) {
            int item = base + lane;
            if (item < 36) {
                int k9 = item >> 2, s = item & 3;
                int kk = 9 + k9;
                float dd = wdd[mu][kk], dh = wdh[mu][kk];
                float pd = dd * V1[kk][s];
                float ph = dd*dd*(V2[kk][s] + Qn[k9][s]) + dh*V1[kk][s];
                int at = jlA(k9, A);
                wpd[mu][at][s] = pd;
                wph[mu][at][s] = ph;
            }
        }
        __syncwarp();

        {
            int s = lane & 3, g = lane >> 2;
            float td = 0.f, th = 0.f;
            for (int k = g; k < 9; k += 8) {
                int j = jlA(k, A);
                float ddc = wdd[mu][k], dhc = wdh[mu][k];
                float rdc = rad1k[k]*ddc;
                float rhc = fmaf(rad2k[k], ddc*ddc, rad1k[k]*dhc);
                td = fmaf(pv[j][s], rdc, td);
                th = fmaf(2.f*wpd[mu][j][s], rdc, fmaf(pv[j][s], rhc, th));
                float ddn = wdd[mu][9+k], dhn = wdh[mu][9+k];
                float rdn = rad1k[9+k]*ddn;
                float rhn = fmaf(rad2k[9+k], ddn*ddn, rad1k[9+k]*dhn);
                td = fmaf(pv[A][s], rdn, td);
                th = fmaf(2.f*wpd[mu][A][s], rdn, fmaf(pv[A][s], rhn, th));
            }
            for (int at = g; at < NATOMS; at += 8) {
                td = fmaf(wpd[mu][at][s], Rr[at], td);
                th = fmaf(wph[mu][at][s], Rr[at], th);
            }
            #pragma unroll
            for (int off = 4; off < 32; off <<= 1) {
                td += __shfl_xor_sync(FULLM, td, off);
                th += __shfl_xor_sync(FULLM, th, off);
            }
            if (lane < 4) {
                Bsh[mu][lane] = td;
                Hsh[mu][lane] = th;
            }
        }
    }
    __syncthreads();

    // -------- P7: single-level tail, warp 0 only --------
    if (tid >= 32) return;
    if (tid < NSTATES) {
        int s = tid;
        float T0 = Tval[0];
        float acc = 0.f;
        #pragma unroll
        for (int mu = 0; mu < 3; mu++) {
            float Bv = Bsh[mu][s], Hv = Hsh[mu][s];
            acc += (s == 0) ? (2.f*Bv*Bv + 2.f*T0*Hv) : Hv;
        }
        g_kin[(c*NATOMS + A)*NSTATES + s] = s_mass * acc;
        if (A == 0) g_T[c*NSTATES + s] = Tval[s];
    }
    __threadfence();
    __syncwarp();
    int flag = 0;
    if (tid == 0) flag = (atomicAdd(&g_fin, 1) == NBLOCKS - 1);
    flag = __shfl_sync(FULLM, flag, 0);
    if (!flag) return;
    __threadfence();
    // lane = (config, state): cc = tid>>2, s = tid&3  (32 lanes = 8x4)
    const int cc = tid >> 2, s = tid & 3;
    volatile float* gk = g_kin;
    volatile float* gt = g_T;
    float kin = 0.f;
    #pragma unroll
    for (int a = 0; a < NATOMS; a++)
        kin += gk[(cc*NATOMS + a)*NSTATES + s];
    kin *= -0.5f;
    float Ts = gt[cc*NSTATES + s];
    float T0 = __shfl_sync(FULLM, Ts, tid & ~3);
    float psi = (s == 0) ? T0*T0 : Ts;
    float pe  = pot[cc] - pot[NCONF-1];
    float vib = (kin + psi*pe) / psi;
    float dvv = vib - s_el[s];
    float l = dvv*dvv;
    #pragma unroll
    for (int off = 16; off > 0; off >>= 1)
        l += __shfl_xor_sync(FULLM, l, off);
    if (tid == 0) {
        out[0] = l;
        g_fin = 0;   // reset for next graph replay
    }
}

extern "C" void kernel_launch(void* const* d_in, const int* in_sizes, int n_in,
                              void* d_out, int out_size)
{
    // metadata order: eigen_weight, pot, cart, numatoms, species, massrev,
    //                 atom_index, shifts, W1, B1, W2, Emb, elevel
    const float* pot     = (const float*)d_in[1];
    const float* cart    = (const float*)d_in[2];
    const int*   species = (const int*)  d_in[4];
    const float* massrev = (const float*)d_in[5];
    const float* W1      = (const float*)d_in[8];
    const float* B1      = (const float*)d_in[9];
    const float* W2      = (const float*)d_in[10];
    const float* Emb     = (const float*)d_in[11];
    const float* elevel  = (const float*)d_in[12];

    fused_kernel<<<NBLOCKS, NT>>>(pot, cart, species, massrev,
                                  W1, B1, W2, Emb, elevel, (float*)d_out);
}

// round 9
// speedup vs baseline: 1.0197x; 1.0197x over previous
#include <cuda_runtime.h>

#define NCONF   8
#define NATOMS  10
#define NSTATES 4
#define NBASIS  24
#define HIDDEN  48
#define NTYPES  4
#define PPC     90            // ordered pairs, contiguous: p = i*9 + (j - (j>i))
#define NT      512
#define NBLOCKS (NCONF*NATOMS)

#define PI_F 3.14159265358979323846f
#define CUT  6.0f
#define KARG (PI_F/CUT)
#define AL   1.5f
#define DLT  (CUT/23.0f)
#define FULLM 0xffffffffu

// cross-block scratch (no cudaMalloc allowed)
__device__ float g_kin[NCONF*NATOMS*NSTATES];
__device__ float g_T[NCONF*NSTATES];
__device__ int   g_fin;

__device__ __forceinline__ int jlA(int t, int A) { return t + (t >= A); }

__device__ __forceinline__ float fast_tanh(float u) {
    float ex = __expf(2.f*u);
    return 1.f - __fdividef(2.f, ex + 1.f);
}

__global__ void __launch_bounds__(NT, 1)
fused_kernel(const float* __restrict__ pot, const float* __restrict__ cart,
             const int* __restrict__ species, const float* __restrict__ massrev,
             const float* __restrict__ W1, const float* __restrict__ B1,
             const float* __restrict__ W2, const float* __restrict__ Emb,
             const float* __restrict__ elevel, float* __restrict__ out)
{
    __shared__ __align__(16) float W1s[NBASIS][52];
    __shared__ __align__(16) float W2s[HIDDEN][4];
    __shared__ float B1all[NTYPES][48];
    __shared__ float EmbAll[NTYPES][4];
    __shared__ int   s_sp[NATOMS];
    __shared__ float s_cart[NATOMS*3];
    __shared__ float s_pe, s_mass, s_el[4];
    __shared__ float G0[PPC][25];
    __shared__ float radv[PPC];
    __shared__ float G1k[18][25], G2k[18][25];
    __shared__ float rad1k[18], rad2k[18];
    __shared__ float wdd[3][18], wdh[3][18];
    __shared__ float densv[NATOMS][25];
    __shared__ float Rr[NATOMS];
    __shared__ float tval[NATOMS][49], f1a[NATOMS][49], f2a[NATOMS][49];
    __shared__ __align__(16) float U1[18][52], U2[18][52];
    __shared__ float pv[NATOMS][4];
    __shared__ float V1[18][4], V2[18][4], Qn[9][4];
    __shared__ float QA[3][4];
    __shared__ float wpd[3][NATOMS][4], wph[3][NATOMS][4];
    __shared__ float Tval[4];
    __shared__ float Bsh[3][4], Hsh[3][4];

    const int tid  = threadIdx.x;
    const int w    = tid >> 5;
    const int lane = tid & 31;
    const int c    = blockIdx.x / NATOMS;
    const int A    = blockIdx.x % NATOMS;

    // -------- P1: all global loads up front, no dependent chains --------
    if (tid < NBASIS*HIDDEN)
        W1s[tid / HIDDEN][tid % HIDDEN] = W1[tid];
    {
        int i2 = tid + NT;
        if (i2 < NBASIS*HIDDEN) W1s[i2 / HIDDEN][i2 % HIDDEN] = W1[i2];
        int i3 = tid + 2*NT;
        if (i3 < NBASIS*HIDDEN) W1s[i3 / HIDDEN][i3 % HIDDEN] = W1[i3];
    }
    if (tid < HIDDEN*NSTATES) {
        W2s[tid >> 2][tid & 3] = W2[tid];
        B1all[tid / 48][tid % 48] = B1[tid];        // all 4 species rows
    } else if (tid < 192 + NTYPES*NSTATES) {
        int i = tid - 192;
        EmbAll[i >> 2][i & 3] = Emb[i];
    } else if (tid < 208 + NATOMS) {
        s_sp[tid - 208] = species[c*NATOMS + (tid - 208)];
    } else if (tid >= 218 && tid < 218 + NATOMS*3) {
        s_cart[tid - 218] = cart[c*NATOMS*3 + (tid - 218)];
    } else if (tid == 248) {
        s_mass = massrev[c*NATOMS + A];
    } else if (tid == 249) {
        s_pe = pot[c] - pot[NCONF-1];
    } else if (tid >= 250 && tid < 250 + NSTATES) {
        s_el[tid - 250] = elevel[tid - 250];
    }
    __syncthreads();

    // -------- P2: pair geometry (G0), A-pair jets on separate warp --------
    if (tid < PPC) {
        const int p = tid;
        const int i = p / 9, jr = p % 9;
        const int j = jr + (jr >= i);
        float dx = s_cart[j*3+0] - s_cart[i*3+0];
        float dy = s_cart[j*3+1] - s_cart[i*3+1];
        float dz = s_cart[j*3+2] - s_cart[i*3+2];
        float d2 = fmaf(dx, dx, fmaf(dy, dy, dz*dz));
        float d  = sqrtf(d2);
        float arg = d * KARG;
        float sn = __sinf(arg), cs = __cosf(arg);
        radv[p] = sn*sn*sn;
        float f0 = (d < CUT) ? 0.5f*(cs + 1.f) : 0.f;

        // rbf via 4 independent 6-step recurrences
        const float gg = __expf(-2.f*AL*DLT*DLT);
        float gg2 = gg*gg, gg3 = gg2*gg, gg6 = gg3*gg3;
        float tc = __expf(fmaf(2.f*AL*DLT, d, -AL*DLT*DLT));
        float t0 = tc, t1 = tc*gg6, t2 = t1*gg6, t3 = t2*gg6;
        float rb0  = __expf(-AL*d2);
        float d6   = d -  6.f*DLT; float rb6  = __expf(-AL*d6*d6);
        float d12  = d - 12.f*DLT; float rb12 = __expf(-AL*d12*d12);
        float d18  = d - 18.f*DLT; float rb18 = __expf(-AL*d18*d18);
        #pragma unroll
        for (int i2 = 0; i2 < 6; i2++) {
            G0[p][i2]      = rb0 *f0;
            G0[p][6 + i2]  = rb6 *f0;
            G0[p][12 + i2] = rb12*f0;
            G0[p][18 + i2] = rb18*f0;
            rb0 *= t0; rb6 *= t1; rb12 *= t2; rb18 *= t3;
            t0 *= gg; t1 *= gg; t2 *= gg; t3 *= gg;
        }
    } else if (tid >= 96 && tid < 96 + 18) {
        const int k   = tid - 96;
        const bool isC = (k < 9);
        const int i = isC ? A : jlA(k - 9, A);
        const int j = isC ? jlA(k, A) : A;
        float dx = s_cart[j*3+0] - s_cart[i*3+0];
        float dy = s_cart[j*3+1] - s_cart[i*3+1];
        float dz = s_cart[j*3+2] - s_cart[i*3+2];
        float d2 = fmaf(dx, dx, fmaf(dy, dy, dz*dz));
        float d  = sqrtf(d2);
        float arg = d * KARG;
        float sn = __sinf(arg), cs = __cosf(arg);
        float f0, fd1, fd2;
        if (d < CUT) {
            f0  = 0.5f*(cs + 1.f);
            fd1 = -0.5f*KARG*sn;
            fd2 = -0.5f*KARG*KARG*cs;
        } else { f0 = 0.f; fd1 = 0.f; fd2 = 0.f; }
        rad1k[k] = 3.f*sn*sn*cs * KARG;
        rad2k[k] = (6.f*sn*cs*cs - 3.f*sn*sn*sn) * (KARG*KARG);
        float invd = __frcp_rn(d);
        float sgn = isC ? -1.f : 1.f;
        float ex = dx*invd, ey = dy*invd, ez = dz*invd;
        wdd[0][k] = sgn*ex; wdh[0][k] = (1.f - ex*ex)*invd;
        wdd[1][k] = sgn*ey; wdh[1][k] = (1.f - ey*ey)*invd;
        wdd[2][k] = sgn*ez; wdh[2][k] = (1.f - ez*ez)*invd;

        const float gg = __expf(-2.f*AL*DLT*DLT);
        float gg2 = gg*gg, gg3 = gg2*gg, gg6 = gg3*gg3;
        float tc = __expf(fmaf(2.f*AL*DLT, d, -AL*DLT*DLT));
        float t0 = tc, t1 = tc*gg6, t2 = t1*gg6, t3 = t2*gg6;
        float rb0  = __expf(-AL*d2);
        float dd6  = d -  6.f*DLT; float rb6  = __expf(-AL*dd6*dd6);
        float dd12 = d - 12.f*DLT; float rb12 = __expf(-AL*dd12*dd12);
        float dd18 = d - 18.f*DLT; float rb18 = __expf(-AL*dd18*dd18);
        #pragma unroll
        for (int i2 = 0; i2 < 6; i2++) {
            #pragma unroll
            for (int sub = 0; sub < 4; sub++) {
                int b = sub*6 + i2;
                float rb = (sub==0) ? rb0 : (sub==1) ? rb6 : (sub==2) ? rb12 : rb18;
                float t  = d - (float)b*DLT;
                float r1 = -2.f*AL*t*rb;
                float r2 = (4.f*AL*AL*t*t - 2.f*AL)*rb;
                G1k[k][b] = r1*f0 + rb*fd1;
                G2k[k][b] = r2*f0 + 2.f*r1*fd1 + rb*fd2;
            }
            rb0 *= t0; rb6 *= t1; rb12 *= t2; rb18 *= t3;
            t0 *= gg; t1 *= gg; t2 *= gg; t3 *= gg;
        }
    }
    __syncthreads();

    // -------- P3: U1/U2 (b-split, 432 threads) + densv/Rr (warps 14-15) --------
    if (tid < 448) {
        const int idx = tid;
        const bool valid = idx < 432;
        int k  = idx / 24; if (k > 17) k = 17;
        const int rem = idx % 24;
        const int hq = (rem >> 1) * 4;
        const int bhalf = rem & 1;
        const int b0 = bhalf * 12;
        float a0=0,a1=0,a2=0,a3=0, c0=0,c1=0,c2=0,c3=0;
        #pragma unroll
        for (int bi = 0; bi < 12; bi++) {
            int b = b0 + bi;
            float g1 = G1k[k][b], g2 = G2k[k][b];
            float4 wv = *(const float4*)&W1s[b][hq];
            a0 = fmaf(g1, wv.x, a0); a1 = fmaf(g1, wv.y, a1);
            a2 = fmaf(g1, wv.z, a2); a3 = fmaf(g1, wv.w, a3);
            c0 = fmaf(g2, wv.x, c0); c1 = fmaf(g2, wv.y, c1);
            c2 = fmaf(g2, wv.z, c2); c3 = fmaf(g2, wv.w, c3);
        }
        a0 += __shfl_xor_sync(FULLM, a0, 1);
        a1 += __shfl_xor_sync(FULLM, a1, 1);
        a2 += __shfl_xor_sync(FULLM, a2, 1);
        a3 += __shfl_xor_sync(FULLM, a3, 1);
        c0 += __shfl_xor_sync(FULLM, c0, 1);
        c1 += __shfl_xor_sync(FULLM, c1, 1);
        c2 += __shfl_xor_sync(FULLM, c2, 1);
        c3 += __shfl_xor_sync(FULLM, c3, 1);
        if (valid && bhalf == 0) {
            U1[k][hq]=a0; U1[k][hq+1]=a1; U1[k][hq+2]=a2; U1[k][hq+3]=a3;
            U2[k][hq]=c0; U2[k][hq+1]=c1; U2[k][hq+2]=c2; U2[k][hq+3]=c3;
        }
    } else {
        for (int item = tid - 448; item < NATOMS*NBASIS + NATOMS; item += 64) {
            if (item < NATOMS*NBASIS) {
                int at = item / NBASIS, b = item % NBASIS;
                float a0 = 0.f, a1 = 0.f;
                #pragma unroll
                for (int r = 0; r < 8; r += 2) {
                    a0 += G0[at*9 + r][b];
                    a1 += G0[at*9 + r + 1][b];
                }
                densv[at][b] = a0 + a1 + G0[at*9 + 8][b];
            } else {
                int at = item - NATOMS*NBASIS;
                float r = 0.f;
                #pragma unroll
                for (int j = 0; j < NATOMS; j++)
                    if (j != at) r += radv[j*9 + (at - (at > j))];
                Rr[at] = r;
            }
        }
    }
    __syncthreads();

    // -------- P4: tanh value path, 1 item per thread --------
    if (tid < NATOMS*HIDDEN) {
        int at = tid / HIDDEN, hh = tid % HIDDEN;
        float u0 = B1all[s_sp[at]][hh], u1 = 0.f, u2 = 0.f, u3 = 0.f;
        #pragma unroll
        for (int b = 0; b < NBASIS; b += 4) {
            u0 = fmaf(densv[at][b  ], W1s[b  ][hh], u0);
            u1 = fmaf(densv[at][b+1], W1s[b+1][hh], u1);
            u2 = fmaf(densv[at][b+2], W1s[b+2][hh], u2);
            u3 = fmaf(densv[at][b+3], W1s[b+3][hh], u3);
        }
        float t  = fast_tanh((u0 + u1) + (u2 + u3));
        float f1 = 1.f - t*t;
        tval[at][hh] = t;
        f1a[at][hh]  = f1;
        f2a[at][hh]  = -2.f*t*f1;
    }
    __syncthreads();

    // -------- P5: pv (hh-halves), V1/V2 (hh-quarters), Qn (hh-halves), QA --------
    if (w < 3) {
        // pv: (at, s, half) on 80 threads
        const bool valid = tid < 80;
        int at = tid >> 3; if (at > 9) at = 9;
        const int s = (tid >> 1) & 3;
        const int half = tid & 1;
        const int h0 = half * 24;
        float a0 = 0.f, a1 = 0.f;
        #pragma unroll
        for (int hi = 0; hi < 24; hi += 2) {
            a0 = fmaf(tval[at][h0+hi  ], W2s[h0+hi  ][s], a0);
            a1 = fmaf(tval[at][h0+hi+1], W2s[h0+hi+1][s], a1);
        }
        float v = a0 + a1;
        v += __shfl_xor_sync(FULLM, v, 1);
        if (valid && half == 0) pv[at][s] = v + EmbAll[s_sp[at]][s];
    } else if (w >= 4 && w <= 8) {
        // V1/V2: (k, which, quarter) on 144 threads (tid 128..271)
        const int idx = tid - 128;
        const bool valid = idx < 144;
        int k = idx >> 3; if (k > 17) k = 17;
        const int which = (idx >> 2) & 1;
        const int quarter = idx & 3;
        const int cen = (k < 9) ? A : jlA(k - 9, A);
        const int h0 = quarter * 12;
        float v0=0,v1=0,v2=0,v3=0;
        #pragma unroll
        for (int hi = 0; hi < 12; hi++) {
            int hh = h0 + hi;
            float u = (which ? U2[k][hh] : U1[k][hh]) * f1a[cen][hh];
            float4 wv = *(const float4*)&W2s[hh][0];
            v0 = fmaf(u, wv.x, v0); v1 = fmaf(u, wv.y, v1);
            v2 = fmaf(u, wv.z, v2); v3 = fmaf(u, wv.w, v3);
        }
        #pragma unroll
        for (int off = 1; off <= 2; off <<= 1) {
            v0 += __shfl_xor_sync(FULLM, v0, off);
            v1 += __shfl_xor_sync(FULLM, v1, off);
            v2 += __shfl_xor_sync(FULLM, v2, off);
            v3 += __shfl_xor_sync(FULLM, v3, off);
        }
        if (valid && quarter == 0) {
            if (which) { V2[k][0]=v0; V2[k][1]=v1; V2[k][2]=v2; V2[k][3]=v3; }
            else       { V1[k][0]=v0; V1[k][1]=v1; V1[k][2]=v2; V1[k][3]=v3; }
        }
    } else if (w == 9) {
        // Qn: (k9, half) = 18 items on one warp; lanes 18-31 padded (no write)
        const int idx = lane;
        int k9 = idx >> 1; if (k9 > 8) k9 = 8;
        const int half = idx & 1;
        const int cen = jlA(k9, A);
        const int h0 = half * 24;
        float q0=0,q1=0,q2=0,q3=0;
        #pragma unroll
        for (int hi = 0; hi < 24; hi++) {
            int hh = h0 + hi;
            float u = U1[9+k9][hh];
            float cf = f2a[cen][hh] * u * u;
            float4 wv = *(const float4*)&W2s[hh][0];
            q0 = fmaf(cf, wv.x, q0); q1 = fmaf(cf, wv.y, q1);
            q2 = fmaf(cf, wv.z, q2); q3 = fmaf(cf, wv.w, q3);
        }
        q0 += __shfl_xor_sync(FULLM, q0, 1);
        q1 += __shfl_xor_sync(FULLM, q1, 1);
        q2 += __shfl_xor_sync(FULLM, q2, 1);
        q3 += __shfl_xor_sync(FULLM, q3, 1);
        if (idx < 18 && half == 0) {
            Qn[k9][0]=q0; Qn[k9][1]=q1; Qn[k9][2]=q2; Qn[k9][3]=q3;
        }
    } else if (w >= 10 && w <= 12) {
        // QA cross term for perturbed atom A, one warp per mu
        const int mu = w - 10;
        float q0=0,q1=0,q2=0,q3=0;
        #pragma unroll
        for (int rep = 0; rep < 2; rep++) {
            int hh = lane + rep*32;
            if (hh < HIDDEN) {
                float ud = 0.f;
                #pragma unroll
                for (int k = 0; k < 9; k++)
                    ud = fmaf(wdd[mu][k], U1[k][hh], ud);
                float cf = f2a[A][hh] * ud * ud;
                float4 wv = *(const float4*)&W2s[hh][0];
                q0 = fmaf(cf, wv.x, q0); q1 = fmaf(cf, wv.y, q1);
                q2 = fmaf(cf, wv.z, q2); q3 = fmaf(cf, wv.w, q3);
            }
        }
        #pragma unroll
        for (int off = 16; off > 0; off >>= 1) {
            q0 += __shfl_xor_sync(FULLM, q0, off);
            q1 += __shfl_xor_sync(FULLM, q1, off);
            q2 += __shfl_xor_sync(FULLM, q2, off);
            q3 += __shfl_xor_sync(FULLM, q3, off);
        }
        if (lane == 0) { QA[mu][0]=q0; QA[mu][1]=q1; QA[mu][2]=q2; QA[mu][3]=q3; }
    }
    __syncthreads();

    // -------- P6: directions (warps 0-2) + Tval (tid 96..99) --------
    if (tid >= 96 && tid < 96 + NSTATES) {
        int s = tid - 96;
        float acc = 0.f;
        #pragma unroll
        for (int j = 0; j < NATOMS; j++)
            acc = fmaf(pv[j][s], Rr[j], acc);
        Tval[s] = acc;
    }
    if (w < 3) {
        const int mu = w;
        float accA = 0.f;
        if (lane < 8) {
            int s = lane & 3;
            bool second = lane >= 4;
            #pragma unroll
            for (int k = 0; k < 9; k++) {
                float dd = wdd[mu][k], dh = wdh[mu][k];
                accA += second ? fmaf(dd*dd, V2[k][s], dh*V1[k][s])
                               : dd*V1[k][s];
            }
        }
        if (lane < 4)      wpd[mu][A][lane]   = accA;
        else if (lane < 8) wph[mu][A][lane-4] = accA + QA[mu][lane-4];
        __syncwarp();

        #pragma unroll
        for (int base = 0; base < 36; base += 32) {
            int item = base + lane;
            if (item < 36) {
                int k9 = item >> 2, s = item & 3;
                int kk = 9 + k9;
                float dd = wdd[mu][kk], dh = wdh[mu][kk];
                float pd = dd * V1[kk][s];
                float ph = dd*dd*(V2[kk][s] + Qn[k9][s]) + dh*V1[kk][s];
                int at = jlA(k9, A);
                wpd[mu][at][s] = pd;
                wph[mu][at][s] = ph;
            }
        }
        __syncwarp();

        {
            int s = lane & 3, g = lane >> 2;
            float td = 0.f, th = 0.f;
            for (int k = g; k < 9; k += 8) {
                int j = jlA(k, A);
                float ddc = wdd[mu][k], dhc = wdh[mu][k];
                float rdc = rad1k[k]*ddc;
                float rhc = fmaf(rad2k[k], ddc*ddc, rad1k[k]*dhc);
                td = fmaf(pv[j][s], rdc, td);
                th = fmaf(2.f*wpd[mu][j][s], rdc, fmaf(pv[j][s], rhc, th));
                float ddn = wdd[mu][9+k], dhn = wdh[mu][9+k];
                float rdn = rad1k[9+k]*ddn;
                float rhn = fmaf(rad2k[9+k], ddn*ddn, rad1k[9+k]*dhn);
                td = fmaf(pv[A][s], rdn, td);
                th = fmaf(2.f*wpd[mu][A][s], rdn, fmaf(pv[A][s], rhn, th));
            }
            for (int at = g; at < NATOMS; at += 8) {
                td = fmaf(wpd[mu][at][s], Rr[at], td);
                th = fmaf(wph[mu][at][s], Rr[at], th);
            }
            #pragma unroll
            for (int off = 4; off < 32; off <<= 1) {
                td += __shfl_xor_sync(FULLM, td, off);
                th += __shfl_xor_sync(FULLM, th, off);
            }
            if (lane < 4) {
                Bsh[mu][lane] = td;
                Hsh[mu][lane] = th;
            }
        }
    }
    __syncthreads();

    // -------- P7: single-level tail, warp 0 only --------
    if (tid >= 32) return;
    if (tid < NSTATES) {
        int s = tid;
        float T0 = Tval[0];
        float acc = 0.f;
        #pragma unroll
        for (int mu = 0; mu < 3; mu++) {
            float Bv = Bsh[mu][s], Hv = Hsh[mu][s];
            acc += (s == 0) ? (2.f*Bv*Bv + 2.f*T0*Hv) : Hv;
        }
        g_kin[(c*NATOMS + A)*NSTATES + s] = s_mass * acc;
        if (A == 0) g_T[c*NSTATES + s] = Tval[s];
    }
    __threadfence();
    __syncwarp();
    int flag = 0;
    if (tid == 0) flag = (atomicAdd(&g_fin, 1) == NBLOCKS - 1);
    flag = __shfl_sync(FULLM, flag, 0);
    if (!flag) return;
    __threadfence();
    // lane = (config, state): cc = tid>>2, s = tid&3  (32 lanes = 8x4)
    const int cc = tid >> 2, s = tid & 3;
    volatile float* gk = g_kin;
    volatile float* gt = g_T;
    float kin = 0.f;
    #pragma unroll
    for (int a = 0; a < NATOMS; a++)
        kin += gk[(cc*NATOMS + a)*NSTATES + s];
    kin *= -0.5f;
    float Ts = gt[cc*NSTATES + s];
    float T0 = __shfl_sync(FULLM, Ts, tid & ~3);
    float psi = (s == 0) ? T0*T0 : Ts;
    float pe  = pot[cc] - pot[NCONF-1];
    float vib = (kin + psi*pe) / psi;
    float dvv = vib - s_el[s];
    float l = dvv*dvv;
    #pragma unroll
    for (int off = 16; off > 0; off >>= 1)
        l += __shfl_xor_sync(FULLM, l, off);
    if (tid == 0) {
        out[0] = l;
        g_fin = 0;   // reset for next graph replay
    }
}

extern "C" void kernel_launch(void* const* d_in, const int* in_sizes, int n_in,
                              void* d_out, int out_size)
{
    // metadata order: eigen_weight, pot, cart, numatoms, species, massrev,
    //                 atom_index, shifts, W1, B1, W2, Emb, elevel
    const float* pot     = (const float*)d_in[1];
    const float* cart    = (const float*)d_in[2];
    const int*   species = (const int*)  d_in[4];
    const float* massrev = (const float*)d_in[5];
    const float* W1      = (const float*)d_in[8];
    const float* B1      = (const float*)d_in[9];
    const float* W2      = (const float*)d_in[10];
    const float* Emb     = (const float*)d_in[11];
    const float* elevel  = (const float*)d_in[12];

    fused_kernel<<<NBLOCKS, NT>>>(pot, cart, species, massrev,
                                  W1, B1, W2, Emb, elevel, (float*)d_out);
}

// round 10
// speedup vs baseline: 1.1994x; 1.1763x over previous
#include <cuda_runtime.h>

#define NCONF   8
#define NATOMS  10
#define NSTATES 4
#define NBASIS  24
#define HIDDEN  48
#define NTYPES  4
#define PPC     90            // ordered pairs, contiguous: p = i*9 + (j - (j>i))
#define NT      512
#define NBLOCKS (NCONF*NATOMS)

#define PI_F 3.14159265358979323846f
#define CUT  6.0f
#define KARG (PI_F/CUT)
#define AL   1.5f
#define DLT  (CUT/23.0f)
#define FULLM 0xffffffffu

// cross-block scratch (no cudaMalloc allowed)
__device__ float g_kin[NCONF*NATOMS*NSTATES];
__device__ float g_T[NCONF*NSTATES];
__device__ int   g_fin;

__device__ __forceinline__ int jlA(int t, int A) { return t + (t >= A); }

__device__ __forceinline__ float fast_tanh(float u) {
    float ex = __expf(2.f*u);
    return 1.f - __fdividef(2.f, ex + 1.f);
}

__global__ void __launch_bounds__(NT, 1)
fused_kernel(const float* __restrict__ pot, const float* __restrict__ cart,
             const int* __restrict__ species, const float* __restrict__ massrev,
             const float* __restrict__ W1, const float* __restrict__ B1,
             const float* __restrict__ W2, const float* __restrict__ Emb,
             const float* __restrict__ elevel, float* __restrict__ out)
{
    __shared__ __align__(16) float W1s[NBASIS][52];
    __shared__ __align__(16) float W2s[HIDDEN][4];
    __shared__ float B1all[NTYPES][48];
    __shared__ float EmbAll[NTYPES][4];
    __shared__ int   s_sp[NATOMS];
    __shared__ float s_cart[NATOMS*3];
    __shared__ float s_pe, s_mass, s_el[4];
    __shared__ float G0[PPC][25];
    __shared__ float radv[PPC];
    __shared__ float G1k[18][25], G2k[18][25];
    __shared__ float rad1k[18], rad2k[18];
    __shared__ float wdd[3][18], wdh[3][18];
    __shared__ float densv[NATOMS][25];
    __shared__ float Rr[NATOMS];
    __shared__ float tval[NATOMS][49], f1a[NATOMS][49], f2a[NATOMS][49];
    __shared__ __align__(16) float U1[18][52], U2[18][52];
    __shared__ float pv[NATOMS][4];
    __shared__ float V1[18][4], V2[18][4], Qn[9][4];
    __shared__ float QA[3][4];
    __shared__ float wpd[3][NATOMS][4], wph[3][NATOMS][4];
    __shared__ float Tval[4];
    __shared__ float Bsh[3][4], Hsh[3][4];

    const int tid  = threadIdx.x;
    const int w    = tid >> 5;
    const int lane = tid & 31;
    const int c    = blockIdx.x / NATOMS;
    const int A    = blockIdx.x % NATOMS;

    // -------- P1: all global loads up front, no dependent chains --------
    if (tid < NBASIS*HIDDEN)
        W1s[tid / HIDDEN][tid % HIDDEN] = W1[tid];
    {
        int i2 = tid + NT;
        if (i2 < NBASIS*HIDDEN) W1s[i2 / HIDDEN][i2 % HIDDEN] = W1[i2];
        int i3 = tid + 2*NT;
        if (i3 < NBASIS*HIDDEN) W1s[i3 / HIDDEN][i3 % HIDDEN] = W1[i3];
    }
    if (tid < HIDDEN*NSTATES) {
        W2s[tid >> 2][tid & 3] = W2[tid];
        B1all[tid / 48][tid % 48] = B1[tid];        // all 4 species rows
    } else if (tid < 192 + NTYPES*NSTATES) {
        int i = tid - 192;
        EmbAll[i >> 2][i & 3] = Emb[i];
    } else if (tid < 208 + NATOMS) {
        s_sp[tid - 208] = species[c*NATOMS + (tid - 208)];
    } else if (tid >= 218 && tid < 218 + NATOMS*3) {
        s_cart[tid - 218] = cart[c*NATOMS*3 + (tid - 218)];
    } else if (tid == 248) {
        s_mass = massrev[c*NATOMS + A];
    } else if (tid == 249) {
        s_pe = pot[c] - pot[NCONF-1];
    } else if (tid >= 250 && tid < 250 + NSTATES) {
        s_el[tid - 250] = elevel[tid - 250];
    }
    __syncthreads();

    // -------- P2: pair geometry (G0); A-pair jets on 36 threads --------
    if (tid < PPC) {
        const int p = tid;
        const int i = p / 9, jr = p % 9;
        const int j = jr + (jr >= i);
        float dx = s_cart[j*3+0] - s_cart[i*3+0];
        float dy = s_cart[j*3+1] - s_cart[i*3+1];
        float dz = s_cart[j*3+2] - s_cart[i*3+2];
        float d2 = fmaf(dx, dx, fmaf(dy, dy, dz*dz));
        float d  = sqrtf(d2);
        float arg = d * KARG;
        float sn = __sinf(arg), cs = __cosf(arg);
        radv[p] = sn*sn*sn;
        float f0 = (d < CUT) ? 0.5f*(cs + 1.f) : 0.f;

        // rbf via 4 independent 6-step recurrences
        const float gg = __expf(-2.f*AL*DLT*DLT);
        float gg2 = gg*gg, gg3 = gg2*gg, gg6 = gg3*gg3;
        float tc = __expf(fmaf(2.f*AL*DLT, d, -AL*DLT*DLT));
        float t0 = tc, t1 = tc*gg6, t2 = t1*gg6, t3 = t2*gg6;
        float rb0  = __expf(-AL*d2);
        float d6   = d -  6.f*DLT; float rb6  = __expf(-AL*d6*d6);
        float d12  = d - 12.f*DLT; float rb12 = __expf(-AL*d12*d12);
        float d18  = d - 18.f*DLT; float rb18 = __expf(-AL*d18*d18);
        #pragma unroll
        for (int i2 = 0; i2 < 6; i2++) {
            G0[p][i2]      = rb0 *f0;
            G0[p][6 + i2]  = rb6 *f0;
            G0[p][12 + i2] = rb12*f0;
            G0[p][18 + i2] = rb18*f0;
            rb0 *= t0; rb6 *= t1; rb12 *= t2; rb18 *= t3;
            t0 *= gg; t1 *= gg; t2 *= gg; t3 *= gg;
        }
    } else if (tid >= 96 && tid < 96 + 36) {
        // A-pair jets: (k, bhalf) split, 36 threads, independent writes
        const int idx = tid - 96;
        const int k     = idx >> 1;
        const int bhalf = idx & 1;
        const int b0    = bhalf * 12;
        const bool isC = (k < 9);
        const int i = isC ? A : jlA(k - 9, A);
        const int j = isC ? jlA(k, A) : A;
        float dx = s_cart[j*3+0] - s_cart[i*3+0];
        float dy = s_cart[j*3+1] - s_cart[i*3+1];
        float dz = s_cart[j*3+2] - s_cart[i*3+2];
        float d2 = fmaf(dx, dx, fmaf(dy, dy, dz*dz));
        float d  = sqrtf(d2);
        float arg = d * KARG;
        float sn = __sinf(arg), cs = __cosf(arg);
        float f0, fd1, fd2;
        if (d < CUT) {
            f0  = 0.5f*(cs + 1.f);
            fd1 = -0.5f*KARG*sn;
            fd2 = -0.5f*KARG*KARG*cs;
        } else { f0 = 0.f; fd1 = 0.f; fd2 = 0.f; }
        if (bhalf == 0) {
            rad1k[k] = 3.f*sn*sn*cs * KARG;
            rad2k[k] = (6.f*sn*cs*cs - 3.f*sn*sn*sn) * (KARG*KARG);
            float invd = __frcp_rn(d);
            float sgn = isC ? -1.f : 1.f;
            float ex = dx*invd, ey = dy*invd, ez = dz*invd;
            wdd[0][k] = sgn*ex; wdh[0][k] = (1.f - ex*ex)*invd;
            wdd[1][k] = sgn*ey; wdh[1][k] = (1.f - ey*ey)*invd;
            wdd[2][k] = sgn*ez; wdh[2][k] = (1.f - ez*ez)*invd;
        }
        const float gg = __expf(-2.f*AL*DLT*DLT);
        float gg2 = gg*gg, gg3 = gg2*gg, gg6 = gg3*gg3;
        float tc  = __expf(fmaf(2.f*AL*DLT, d, -AL*DLT*DLT));
        float ggb = bhalf ? gg6*gg6 : 1.f;
        float ta = tc * ggb;       // recurrence ratio at b0
        float tb = ta * gg6;       // recurrence ratio at b0+6
        float da  = d - (float)b0*DLT;      float rba = __expf(-AL*da*da);
        float db_ = d - (float)(b0+6)*DLT;  float rbb = __expf(-AL*db_*db_);
        #pragma unroll
        for (int i2 = 0; i2 < 6; i2++) {
            int ba = b0 + i2, bb = b0 + 6 + i2;
            float t_a = d - (float)ba*DLT;
            float r1a = -2.f*AL*t_a*rba;
            float r2a = (4.f*AL*AL*t_a*t_a - 2.f*AL)*rba;
            G1k[k][ba] = r1a*f0 + rba*fd1;
            G2k[k][ba] = r2a*f0 + 2.f*r1a*fd1 + rba*fd2;
            float t_b = d - (float)bb*DLT;
            float r1b = -2.f*AL*t_b*rbb;
            float r2b = (4.f*AL*AL*t_b*t_b - 2.f*AL)*rbb;
            G1k[k][bb] = r1b*f0 + rbb*fd1;
            G2k[k][bb] = r2b*f0 + 2.f*r1b*fd1 + rbb*fd2;
            rba *= ta; rbb *= tb; ta *= gg; tb *= gg;
        }
    }
    __syncthreads();

    // -------- P3: U1/U2 (b-split, 432 threads) + densv/Rr (warps 14-15) --------
    if (tid < 448) {
        const int idx = tid;
        const bool valid = idx < 432;
        int k  = idx / 24; if (k > 17) k = 17;
        const int rem = idx % 24;
        const int hq = (rem >> 1) * 4;
        const int bhalf = rem & 1;
        const int b0 = bhalf * 12;
        float a0=0,a1=0,a2=0,a3=0, c0=0,c1=0,c2=0,c3=0;
        #pragma unroll
        for (int bi = 0; bi < 12; bi++) {
            int b = b0 + bi;
            float g1 = G1k[k][b], g2 = G2k[k][b];
            float4 wv = *(const float4*)&W1s[b][hq];
            a0 = fmaf(g1, wv.x, a0); a1 = fmaf(g1, wv.y, a1);
            a2 = fmaf(g1, wv.z, a2); a3 = fmaf(g1, wv.w, a3);
            c0 = fmaf(g2, wv.x, c0); c1 = fmaf(g2, wv.y, c1);
            c2 = fmaf(g2, wv.z, c2); c3 = fmaf(g2, wv.w, c3);
        }
        a0 += __shfl_xor_sync(FULLM, a0, 1);
        a1 += __shfl_xor_sync(FULLM, a1, 1);
        a2 += __shfl_xor_sync(FULLM, a2, 1);
        a3 += __shfl_xor_sync(FULLM, a3, 1);
        c0 += __shfl_xor_sync(FULLM, c0, 1);
        c1 += __shfl_xor_sync(FULLM, c1, 1);
        c2 += __shfl_xor_sync(FULLM, c2, 1);
        c3 += __shfl_xor_sync(FULLM, c3, 1);
        if (valid && bhalf == 0) {
            U1[k][hq]=a0; U1[k][hq+1]=a1; U1[k][hq+2]=a2; U1[k][hq+3]=a3;
            U2[k][hq]=c0; U2[k][hq+1]=c1; U2[k][hq+2]=c2; U2[k][hq+3]=c3;
        }
    } else {
        for (int item = tid - 448; item < NATOMS*NBASIS + NATOMS; item += 64) {
            if (item < NATOMS*NBASIS) {
                int at = item / NBASIS, b = item % NBASIS;
                float a0 = 0.f, a1 = 0.f;
                #pragma unroll
                for (int r = 0; r < 8; r += 2) {
                    a0 += G0[at*9 + r][b];
                    a1 += G0[at*9 + r + 1][b];
                }
                densv[at][b] = a0 + a1 + G0[at*9 + 8][b];
            } else {
                int at = item - NATOMS*NBASIS;
                float r = 0.f;
                #pragma unroll
                for (int j = 0; j < NATOMS; j++)
                    if (j != at) r += radv[j*9 + (at - (at > j))];
                Rr[at] = r;
            }
        }
    }
    __syncthreads();

    // -------- P4: tanh value path, 1 item per thread --------
    if (tid < NATOMS*HIDDEN) {
        int at = tid / HIDDEN, hh = tid % HIDDEN;
        float u0 = B1all[s_sp[at]][hh], u1 = 0.f, u2 = 0.f, u3 = 0.f;
        #pragma unroll
        for (int b = 0; b < NBASIS; b += 4) {
            u0 = fmaf(densv[at][b  ], W1s[b  ][hh], u0);
            u1 = fmaf(densv[at][b+1], W1s[b+1][hh], u1);
            u2 = fmaf(densv[at][b+2], W1s[b+2][hh], u2);
            u3 = fmaf(densv[at][b+3], W1s[b+3][hh], u3);
        }
        float t  = fast_tanh((u0 + u1) + (u2 + u3));
        float f1 = 1.f - t*t;
        tval[at][hh] = t;
        f1a[at][hh]  = f1;
        f2a[at][hh]  = -2.f*t*f1;
    }
    __syncthreads();

    // -------- P5: pv (hh-halves), V1/V2 (hh-quarters), Qn (hh-halves), QA --------
    if (w < 3) {
        // pv: (at, s, half) on 80 threads
        const bool valid = tid < 80;
        int at = tid >> 3; if (at > 9) at = 9;
        const int s = (tid >> 1) & 3;
        const int half = tid & 1;
        const int h0 = half * 24;
        float a0 = 0.f, a1 = 0.f;
        #pragma unroll
        for (int hi = 0; hi < 24; hi += 2) {
            a0 = fmaf(tval[at][h0+hi  ], W2s[h0+hi  ][s], a0);
            a1 = fmaf(tval[at][h0+hi+1], W2s[h0+hi+1][s], a1);
        }
        float v = a0 + a1;
        v += __shfl_xor_sync(FULLM, v, 1);
        if (valid && half == 0) pv[at][s] = v + EmbAll[s_sp[at]][s];
    } else if (w >= 4 && w <= 8) {
        // V1/V2: (k, which, quarter) on 144 threads (tid 128..271)
        const int idx = tid - 128;
        const bool valid = idx < 144;
        int k = idx >> 3; if (k > 17) k = 17;
        const int which = (idx >> 2) & 1;
        const int quarter = idx & 3;
        const int cen = (k < 9) ? A : jlA(k - 9, A);
        const int h0 = quarter * 12;
        float v0=0,v1=0,v2=0,v3=0;
        #pragma unroll
        for (int hi = 0; hi < 12; hi++) {
            int hh = h0 + hi;
            float u = (which ? U2[k][hh] : U1[k][hh]) * f1a[cen][hh];
            float4 wv = *(const float4*)&W2s[hh][0];
            v0 = fmaf(u, wv.x, v0); v1 = fmaf(u, wv.y, v1);
            v2 = fmaf(u, wv.z, v2); v3 = fmaf(u, wv.w, v3);
        }
        #pragma unroll
        for (int off = 1; off <= 2; off <<= 1) {
            v0 += __shfl_xor_sync(FULLM, v0, off);
            v1 += __shfl_xor_sync(FULLM, v1, off);
            v2 += __shfl_xor_sync(FULLM, v2, off);
            v3 += __shfl_xor_sync(FULLM, v3, off);
        }
        if (valid && quarter == 0) {
            if (which) { V2[k][0]=v0; V2[k][1]=v1; V2[k][2]=v2; V2[k][3]=v3; }
            else       { V1[k][0]=v0; V1[k][1]=v1; V1[k][2]=v2; V1[k][3]=v3; }
        }
    } else if (w == 9) {
        // Qn: (k9, half) = 18 items on one warp; lanes 18-31 padded (no write)
        const int idx = lane;
        int k9 = idx >> 1; if (k9 > 8) k9 = 8;
        const int half = idx & 1;
        const int cen = jlA(k9, A);
        const int h0 = half * 24;
        float q0=0,q1=0,q2=0,q3=0;
        #pragma unroll
        for (int hi = 0; hi < 24; hi++) {
            int hh = h0 + hi;
            float u = U1[9+k9][hh];
            float cf = f2a[cen][hh] * u * u;
            float4 wv = *(const float4*)&W2s[hh][0];
            q0 = fmaf(cf, wv.x, q0); q1 = fmaf(cf, wv.y, q1);
            q2 = fmaf(cf, wv.z, q2); q3 = fmaf(cf, wv.w, q3);
        }
        q0 += __shfl_xor_sync(FULLM, q0, 1);
        q1 += __shfl_xor_sync(FULLM, q1, 1);
        q2 += __shfl_xor_sync(FULLM, q2, 1);
        q3 += __shfl_xor_sync(FULLM, q3, 1);
        if (idx < 18 && half == 0) {
            Qn[k9][0]=q0; Qn[k9][1]=q1; Qn[k9][2]=q2; Qn[k9][3]=q3;
        }
    } else if (w >= 10 && w <= 12) {
        // QA cross term for perturbed atom A, one warp per mu
        const int mu = w - 10;
        float q0=0,q1=0,q2=0,q3=0;
        #pragma unroll
        for (int rep = 0; rep < 2; rep++) {
            int hh = lane + rep*32;
            if (hh < HIDDEN) {
                float ud = 0.f;
                #pragma unroll
                for (int k = 0; k < 9; k++)
                    ud = fmaf(wdd[mu][k], U1[k][hh], ud);
                float cf = f2a[A][hh] * ud * ud;
                float4 wv = *(const float4*)&W2s[hh][0];
                q0 = fmaf(cf, wv.x, q0); q1 = fmaf(cf, wv.y, q1);
                q2 = fmaf(cf, wv.z, q2); q3 = fmaf(cf, wv.w, q3);
            }
        }
        #pragma unroll
        for (int off = 16; off > 0; off >>= 1) {
            q0 += __shfl_xor_sync(FULLM, q0, off);
            q1 += __shfl_xor_sync(FULLM, q1, off);
            q2 += __shfl_xor_sync(FULLM, q2, off);
            q3 += __shfl_xor_sync(FULLM, q3, off);
        }
        if (lane == 0) { QA[mu][0]=q0; QA[mu][1]=q1; QA[mu][2]=q2; QA[mu][3]=q3; }
    }
    __syncthreads();

    // -------- P6: only warps 0-3 continue; the rest exit --------
    if (w >= 4) return;

    if (tid >= 96 && tid < 96 + NSTATES) {
        int s = tid - 96;
        float acc = 0.f;
        #pragma unroll
        for (int j = 0; j < NATOMS; j++)
            acc = fmaf(pv[j][s], Rr[j], acc);
        Tval[s] = acc;
    }
    if (w < 3) {
        const int mu = w;
        float accA = 0.f;
        if (lane < 8) {
            int s = lane & 3;
            bool second = lane >= 4;
            #pragma unroll
            for (int k = 0; k < 9; k++) {
                float dd = wdd[mu][k], dh = wdh[mu][k];
                accA += second ? fmaf(dd*dd, V2[k][s], dh*V1[k][s])
                               : dd*V1[k][s];
            }
        }
        if (lane < 4)      wpd[mu][A][lane]   = accA;
        else if (lane < 8) wph[mu][A][lane-4] = accA + QA[mu][lane-4];
        __syncwarp();

        #pragma unroll
        for (int base = 0; base < 36; base += 32) {
            int item = base + lane;
            if (item < 36) {
                int k9 = item >> 2, s = item & 3;
                int kk = 9 + k9;
                float dd = wdd[mu][kk], dh = wdh[mu][kk];
                float pd = dd * V1[kk][s];
                float ph = dd*dd*(V2[kk][s] + Qn[k9][s]) + dh*V1[kk][s];
                int at = jlA(k9, A);
                wpd[mu][at][s] = pd;
                wph[mu][at][s] = ph;
            }
        }
        __syncwarp();

        {
            int s = lane & 3, g = lane >> 2;
            float td = 0.f, th = 0.f;
            for (int k = g; k < 9; k += 8) {
                int j = jlA(k, A);
                float ddc = wdd[mu][k], dhc = wdh[mu][k];
                float rdc = rad1k[k]*ddc;
                float rhc = fmaf(rad2k[k], ddc*ddc, rad1k[k]*dhc);
                td = fmaf(pv[j][s], rdc, td);
                th = fmaf(2.f*wpd[mu][j][s], rdc, fmaf(pv[j][s], rhc, th));
                float ddn = wdd[mu][9+k], dhn = wdh[mu][9+k];
                float rdn = rad1k[9+k]*ddn;
                float rhn = fmaf(rad2k[9+k], ddn*ddn, rad1k[9+k]*dhn);
                td = fmaf(pv[A][s], rdn, td);
                th = fmaf(2.f*wpd[mu][A][s], rdn, fmaf(pv[A][s], rhn, th));
            }
            for (int at = g; at < NATOMS; at += 8) {
                td = fmaf(wpd[mu][at][s], Rr[at], td);
                th = fmaf(wph[mu][at][s], Rr[at], th);
            }
            #pragma unroll
            for (int off = 4; off < 32; off <<= 1) {
                td += __shfl_xor_sync(FULLM, td, off);
                th += __shfl_xor_sync(FULLM, th, off);
            }
            if (lane < 4) {
                Bsh[mu][lane] = td;
                Hsh[mu][lane] = th;
            }
        }
    }
    // named barrier over warps 0-3 only (128 threads)
    asm volatile("bar.sync 1, 128;" ::: "memory");

    // -------- P7: warp 0 only --------
    if (w != 0) return;
    if (tid < NSTATES) {
        int s = tid;
        float T0 = Tval[0];
        float acc = 0.f;
        #pragma unroll
        for (int mu = 0; mu < 3; mu++) {
            float Bv = Bsh[mu][s], Hv = Hsh[mu][s];
            acc += (s == 0) ? (2.f*Bv*Bv + 2.f*T0*Hv) : Hv;
        }
        g_kin[(c*NATOMS + A)*NSTATES + s] = s_mass * acc;
        if (A == 0) g_T[c*NSTATES + s] = Tval[s];
    }
    __threadfence();           // publish g_kin/g_T (all lanes)
    __syncwarp();
    int flag = 0;
    if (lane == 0) {
        int old;
        asm volatile("atom.acq_rel.gpu.add.s32 %0, [%1], 1;"
                     : "=r"(old) : "l"(&g_fin) : "memory");
        flag = (old == NBLOCKS - 1);
    }
    flag = __shfl_sync(FULLM, flag, 0);
    if (!flag) return;
    // acquire from the atomic orders the reads below — no reader fence
    const int cc = tid >> 2, s = tid & 3;   // 32 lanes = 8 configs x 4 states
    volatile float* gk = g_kin;
    volatile float* gt = g_T;
    float kin = 0.f;
    #pragma unroll
    for (int a = 0; a < NATOMS; a++)
        kin += gk[(cc*NATOMS + a)*NSTATES + s];
    kin *= -0.5f;
    float Ts = gt[cc*NSTATES + s];
    float T0 = __shfl_sync(FULLM, Ts, tid & ~3);
    float psi = (s == 0) ? T0*T0 : Ts;
    float pe  = pot[cc] - pot[NCONF-1];
    float vib = (kin + psi*pe) / psi;
    float dvv = vib - s_el[s];
    float l = dvv*dvv;
    #pragma unroll
    for (int off = 16; off > 0; off >>= 1)
        l += __shfl_xor_sync(FULLM, l, off);
    if (tid == 0) {
        out[0] = l;
        g_fin = 0;   // reset for next graph replay
    }
}

extern "C" void kernel_launch(void* const* d_in, const int* in_sizes, int n_in,
                              void* d_out, int out_size)
{
    // metadata order: eigen_weight, pot, cart, numatoms, species, massrev,
    //                 atom_index, shifts, W1, B1, W2, Emb, elevel
    const float* pot     = (const float*)d_in[1];
    const float* cart    = (const float*)d_in[2];
    const int*   species = (const int*)  d_in[4];
    const float* massrev = (const float*)d_in[5];
    const float* W1      = (const float*)d_in[8];
    const float* B1      = (const float*)d_in[9];
    const float* W2      = (const float*)d_in[10];
    const float* Emb     = (const float*)d_in[11];
    const float* elevel  = (const float*)d_in[12];

    fused_kernel<<<NBLOCKS, NT>>>(pot, cart, species, massrev,
                                  W1, B1, W2, Emb, elevel, (float*)d_out);
}

// round 11
// speedup vs baseline: 1.2099x; 1.0087x over previous
#include <cuda_runtime.h>

#define NCONF   8
#define NATOMS  10
#define NSTATES 4
#define NBASIS  24
#define HIDDEN  48
#define NTYPES  4
#define PPC     90            // ordered pairs, contiguous: p = i*9 + (j - (j>i))
#define NT      512
#define NBLOCKS (NCONF*NATOMS)

#define PI_F 3.14159265358979323846f
#define CUT  6.0f
#define KARG (PI_F/CUT)
#define AL   1.5f
#define DLT  (CUT/23.0f)
#define FULLM 0xffffffffu

// cross-block scratch (no cudaMalloc allowed)
// g_kin layout: [c][s][a] so the finalize lane (c,s) reads 10 contiguous floats
__device__ __align__(16) float g_kin[NCONF*NSTATES*NATOMS];
__device__ float g_T[NCONF*NSTATES];
__device__ int   g_fin;

__device__ __forceinline__ int jlA(int t, int A) { return t + (t >= A); }

__device__ __forceinline__ float fast_tanh(float u) {
    float ex = __expf(2.f*u);
    return 1.f - __fdividef(2.f, ex + 1.f);
}

__global__ void __launch_bounds__(NT, 1)
fused_kernel(const float* __restrict__ pot, const float* __restrict__ cart,
             const int* __restrict__ species, const float* __restrict__ massrev,
             const float* __restrict__ W1, const float* __restrict__ B1,
             const float* __restrict__ W2, const float* __restrict__ Emb,
             const float* __restrict__ elevel, float* __restrict__ out)
{
    __shared__ __align__(16) float W1s[NBASIS][52];
    __shared__ __align__(16) float W2s[HIDDEN][4];
    __shared__ float B1all[NTYPES][48];
    __shared__ float EmbAll[NTYPES][4];
    __shared__ int   s_sp[NATOMS];
    __shared__ float s_cart[NATOMS*3];
    __shared__ float s_mass, s_el[4];
    __shared__ float G0[PPC][25];
    __shared__ float radv[PPC];
    __shared__ float G1k[18][25], G2k[18][25];
    __shared__ float rad1k[18], rad2k[18];
    __shared__ float wdd[3][18], wdh[3][18];
    __shared__ float densv[NATOMS][25];
    __shared__ float Rr[NATOMS];
    __shared__ float tval[NATOMS][49], f1a[NATOMS][49], f2a[NATOMS][49];
    __shared__ __align__(16) float U1[18][52], U2[18][52];
    __shared__ float pv[NATOMS][4];
    __shared__ float V1[18][4], V2[18][4], Qn[9][4];
    __shared__ float QA[3][4];
    __shared__ float wpd[3][NATOMS][4], wph[3][NATOMS][4];
    __shared__ float Tval[4];
    __shared__ float Bsh[3][4], Hsh[3][4];

    const int tid  = threadIdx.x;
    const int w    = tid >> 5;
    const int lane = tid & 31;
    const int c    = blockIdx.x / NATOMS;
    const int A    = blockIdx.x % NATOMS;

    // prefetch pot for the finalize path (warp 0 only) — retires long before P7
    float potA = 0.f, potLast = 0.f;
    if (w == 0) { potA = pot[lane >> 2]; potLast = pot[NCONF-1]; }

    // -------- P1: all global loads up front, no dependent chains --------
    if (tid < NBASIS*HIDDEN)
        W1s[tid / HIDDEN][tid % HIDDEN] = W1[tid];
    {
        int i2 = tid + NT;
        if (i2 < NBASIS*HIDDEN) W1s[i2 / HIDDEN][i2 % HIDDEN] = W1[i2];
        int i3 = tid + 2*NT;
        if (i3 < NBASIS*HIDDEN) W1s[i3 / HIDDEN][i3 % HIDDEN] = W1[i3];
    }
    if (tid < HIDDEN*NSTATES) {
        W2s[tid >> 2][tid & 3] = W2[tid];
        B1all[tid / 48][tid % 48] = B1[tid];        // all 4 species rows
    } else if (tid < 192 + NTYPES*NSTATES) {
        int i = tid - 192;
        EmbAll[i >> 2][i & 3] = Emb[i];
    } else if (tid < 208 + NATOMS) {
        s_sp[tid - 208] = species[c*NATOMS + (tid - 208)];
    } else if (tid >= 218 && tid < 218 + NATOMS*3) {
        s_cart[tid - 218] = cart[c*NATOMS*3 + (tid - 218)];
    } else if (tid == 248) {
        s_mass = massrev[c*NATOMS + A];
    } else if (tid >= 250 && tid < 250 + NSTATES) {
        s_el[tid - 250] = elevel[tid - 250];
    }
    __syncthreads();

    // -------- P2: pair geometry (G0); A-pair jets on 36 threads --------
    if (tid < PPC) {
        const int p = tid;
        const int i = p / 9, jr = p % 9;
        const int j = jr + (jr >= i);
        float dx = s_cart[j*3+0] - s_cart[i*3+0];
        float dy = s_cart[j*3+1] - s_cart[i*3+1];
        float dz = s_cart[j*3+2] - s_cart[i*3+2];
        float d2 = fmaf(dx, dx, fmaf(dy, dy, dz*dz));
        float d  = sqrtf(d2);
        float arg = d * KARG;
        float sn = __sinf(arg), cs = __cosf(arg);
        radv[p] = sn*sn*sn;
        float f0 = (d < CUT) ? 0.5f*(cs + 1.f) : 0.f;

        // rbf via 4 independent 6-step recurrences
        const float gg = __expf(-2.f*AL*DLT*DLT);
        float gg2 = gg*gg, gg3 = gg2*gg, gg6 = gg3*gg3;
        float tc = __expf(fmaf(2.f*AL*DLT, d, -AL*DLT*DLT));
        float t0 = tc, t1 = tc*gg6, t2 = t1*gg6, t3 = t2*gg6;
        float rb0  = __expf(-AL*d2);
        float d6   = d -  6.f*DLT; float rb6  = __expf(-AL*d6*d6);
        float d12  = d - 12.f*DLT; float rb12 = __expf(-AL*d12*d12);
        float d18  = d - 18.f*DLT; float rb18 = __expf(-AL*d18*d18);
        #pragma unroll
        for (int i2 = 0; i2 < 6; i2++) {
            G0[p][i2]      = rb0 *f0;
            G0[p][6 + i2]  = rb6 *f0;
            G0[p][12 + i2] = rb12*f0;
            G0[p][18 + i2] = rb18*f0;
            rb0 *= t0; rb6 *= t1; rb12 *= t2; rb18 *= t3;
            t0 *= gg; t1 *= gg; t2 *= gg; t3 *= gg;
        }
    } else if (tid >= 96 && tid < 96 + 36) {
        // A-pair jets: (k, bhalf) split, 36 threads, independent writes
        const int idx = tid - 96;
        const int k     = idx >> 1;
        const int bhalf = idx & 1;
        const int b0    = bhalf * 12;
        const bool isC = (k < 9);
        const int i = isC ? A : jlA(k - 9, A);
        const int j = isC ? jlA(k, A) : A;
        float dx = s_cart[j*3+0] - s_cart[i*3+0];
        float dy = s_cart[j*3+1] - s_cart[i*3+1];
        float dz = s_cart[j*3+2] - s_cart[i*3+2];
        float d2 = fmaf(dx, dx, fmaf(dy, dy, dz*dz));
        float d  = sqrtf(d2);
        float arg = d * KARG;
        float sn = __sinf(arg), cs = __cosf(arg);
        float f0, fd1, fd2;
        if (d < CUT) {
            f0  = 0.5f*(cs + 1.f);
            fd1 = -0.5f*KARG*sn;
            fd2 = -0.5f*KARG*KARG*cs;
        } else { f0 = 0.f; fd1 = 0.f; fd2 = 0.f; }
        if (bhalf == 0) {
            rad1k[k] = 3.f*sn*sn*cs * KARG;
            rad2k[k] = (6.f*sn*cs*cs - 3.f*sn*sn*sn) * (KARG*KARG);
            float invd = __frcp_rn(d);
            float sgn = isC ? -1.f : 1.f;
            float ex = dx*invd, ey = dy*invd, ez = dz*invd;
            wdd[0][k] = sgn*ex; wdh[0][k] = (1.f - ex*ex)*invd;
            wdd[1][k] = sgn*ey; wdh[1][k] = (1.f - ey*ey)*invd;
            wdd[2][k] = sgn*ez; wdh[2][k] = (1.f - ez*ez)*invd;
        }
        const float gg = __expf(-2.f*AL*DLT*DLT);
        float gg2 = gg*gg, gg3 = gg2*gg, gg6 = gg3*gg3;
        float tc  = __expf(fmaf(2.f*AL*DLT, d, -AL*DLT*DLT));
        float ggb = bhalf ? gg6*gg6 : 1.f;
        float ta = tc * ggb;       // recurrence ratio at b0
        float tb = ta * gg6;       // recurrence ratio at b0+6
        float da  = d - (float)b0*DLT;      float rba = __expf(-AL*da*da);
        float db_ = d - (float)(b0+6)*DLT;  float rbb = __expf(-AL*db_*db_);
        #pragma unroll
        for (int i2 = 0; i2 < 6; i2++) {
            int ba = b0 + i2, bb = b0 + 6 + i2;
            float t_a = d - (float)ba*DLT;
            float r1a = -2.f*AL*t_a*rba;
            float r2a = (4.f*AL*AL*t_a*t_a - 2.f*AL)*rba;
            G1k[k][ba] = r1a*f0 + rba*fd1;
            G2k[k][ba] = r2a*f0 + 2.f*r1a*fd1 + rba*fd2;
            float t_b = d - (float)bb*DLT;
            float r1b = -2.f*AL*t_b*rbb;
            float r2b = (4.f*AL*AL*t_b*t_b - 2.f*AL)*rbb;
            G1k[k][bb] = r1b*f0 + rbb*fd1;
            G2k[k][bb] = r2b*f0 + 2.f*r1b*fd1 + rbb*fd2;
            rba *= ta; rbb *= tb; ta *= gg; tb *= gg;
        }
    }
    __syncthreads();

    // -------- P3: U1/U2 (b-split, 432 threads) + densv/Rr (warps 14-15) --------
    if (tid < 448) {
        const int idx = tid;
        const bool valid = idx < 432;
        int k  = idx / 24; if (k > 17) k = 17;
        const int rem = idx % 24;
        const int hq = (rem >> 1) * 4;
        const int bhalf = rem & 1;
        const int b0 = bhalf * 12;
        float a0=0,a1=0,a2=0,a3=0, c0=0,c1=0,c2=0,c3=0;
        #pragma unroll
        for (int bi = 0; bi < 12; bi++) {
            int b = b0 + bi;
            float g1 = G1k[k][b], g2 = G2k[k][b];
            float4 wv = *(const float4*)&W1s[b][hq];
            a0 = fmaf(g1, wv.x, a0); a1 = fmaf(g1, wv.y, a1);
            a2 = fmaf(g1, wv.z, a2); a3 = fmaf(g1, wv.w, a3);
            c0 = fmaf(g2, wv.x, c0); c1 = fmaf(g2, wv.y, c1);
            c2 = fmaf(g2, wv.z, c2); c3 = fmaf(g2, wv.w, c3);
        }
        a0 += __shfl_xor_sync(FULLM, a0, 1);
        a1 += __shfl_xor_sync(FULLM, a1, 1);
        a2 += __shfl_xor_sync(FULLM, a2, 1);
        a3 += __shfl_xor_sync(FULLM, a3, 1);
        c0 += __shfl_xor_sync(FULLM, c0, 1);
        c1 += __shfl_xor_sync(FULLM, c1, 1);
        c2 += __shfl_xor_sync(FULLM, c2, 1);
        c3 += __shfl_xor_sync(FULLM, c3, 1);
        if (valid && bhalf == 0) {
            U1[k][hq]=a0; U1[k][hq+1]=a1; U1[k][hq+2]=a2; U1[k][hq+3]=a3;
            U2[k][hq]=c0; U2[k][hq+1]=c1; U2[k][hq+2]=c2; U2[k][hq+3]=c3;
        }
    } else {
        for (int item = tid - 448; item < NATOMS*NBASIS + NATOMS; item += 64) {
            if (item < NATOMS*NBASIS) {
                int at = item / NBASIS, b = item % NBASIS;
                float a0 = 0.f, a1 = 0.f;
                #pragma unroll
                for (int r = 0; r < 8; r += 2) {
                    a0 += G0[at*9 + r][b];
                    a1 += G0[at*9 + r + 1][b];
                }
                densv[at][b] = a0 + a1 + G0[at*9 + 8][b];
            } else {
                int at = item - NATOMS*NBASIS;
                float r = 0.f;
                #pragma unroll
                for (int j = 0; j < NATOMS; j++)
                    if (j != at) r += radv[j*9 + (at - (at > j))];
                Rr[at] = r;
            }
        }
    }
    __syncthreads();

    // -------- P4: tanh value path, 1 item per thread --------
    if (tid < NATOMS*HIDDEN) {
        int at = tid / HIDDEN, hh = tid % HIDDEN;
        float u0 = B1all[s_sp[at]][hh], u1 = 0.f, u2 = 0.f, u3 = 0.f;
        #pragma unroll
        for (int b = 0; b < NBASIS; b += 4) {
            u0 = fmaf(densv[at][b  ], W1s[b  ][hh], u0);
            u1 = fmaf(densv[at][b+1], W1s[b+1][hh], u1);
            u2 = fmaf(densv[at][b+2], W1s[b+2][hh], u2);
            u3 = fmaf(densv[at][b+3], W1s[b+3][hh], u3);
        }
        float t  = fast_tanh((u0 + u1) + (u2 + u3));
        float f1 = 1.f - t*t;
        tval[at][hh] = t;
        f1a[at][hh]  = f1;
        f2a[at][hh]  = -2.f*t*f1;
    }
    __syncthreads();

    // -------- P5: pv (hh-halves), V1/V2 (hh-quarters), Qn (hh-halves), QA --------
    if (w < 3) {
        // pv: (at, s, half) on 80 threads
        const bool valid = tid < 80;
        int at = tid >> 3; if (at > 9) at = 9;
        const int s = (tid >> 1) & 3;
        const int half = tid & 1;
        const int h0 = half * 24;
        float a0 = 0.f, a1 = 0.f;
        #pragma unroll
        for (int hi = 0; hi < 24; hi += 2) {
            a0 = fmaf(tval[at][h0+hi  ], W2s[h0+hi  ][s], a0);
            a1 = fmaf(tval[at][h0+hi+1], W2s[h0+hi+1][s], a1);
        }
        float v = a0 + a1;
        v += __shfl_xor_sync(FULLM, v, 1);
        if (valid && half == 0) pv[at][s] = v + EmbAll[s_sp[at]][s];
    } else if (w >= 4 && w <= 8) {
        // V1/V2: (k, which, quarter) on 144 threads (tid 128..271)
        const int idx = tid - 128;
        const bool valid = idx < 144;
        int k = idx >> 3; if (k > 17) k = 17;
        const int which = (idx >> 2) & 1;
        const int quarter = idx & 3;
        const int cen = (k < 9) ? A : jlA(k - 9, A);
        const int h0 = quarter * 12;
        float v0=0,v1=0,v2=0,v3=0;
        #pragma unroll
        for (int hi = 0; hi < 12; hi++) {
            int hh = h0 + hi;
            float u = (which ? U2[k][hh] : U1[k][hh]) * f1a[cen][hh];
            float4 wv = *(const float4*)&W2s[hh][0];
            v0 = fmaf(u, wv.x, v0); v1 = fmaf(u, wv.y, v1);
            v2 = fmaf(u, wv.z, v2); v3 = fmaf(u, wv.w, v3);
        }
        #pragma unroll
        for (int off = 1; off <= 2; off <<= 1) {
            v0 += __shfl_xor_sync(FULLM, v0, off);
            v1 += __shfl_xor_sync(FULLM, v1, off);
            v2 += __shfl_xor_sync(FULLM, v2, off);
            v3 += __shfl_xor_sync(FULLM, v3, off);
        }
        if (valid && quarter == 0) {
            if (which) { V2[k][0]=v0; V2[k][1]=v1; V2[k][2]=v2; V2[k][3]=v3; }
            else       { V1[k][0]=v0; V1[k][1]=v1; V1[k][2]=v2; V1[k][3]=v3; }
        }
    } else if (w == 9) {
        // Qn: (k9, half) = 18 items on one warp; lanes 18-31 padded (no write)
        const int idx = lane;
        int k9 = idx >> 1; if (k9 > 8) k9 = 8;
        const int half = idx & 1;
        const int cen = jlA(k9, A);
        const int h0 = half * 24;
        float q0=0,q1=0,q2=0,q3=0;
        #pragma unroll
        for (int hi = 0; hi < 24; hi++) {
            int hh = h0 + hi;
            float u = U1[9+k9][hh];
            float cf = f2a[cen][hh] * u * u;
            float4 wv = *(const float4*)&W2s[hh][0];
            q0 = fmaf(cf, wv.x, q0); q1 = fmaf(cf, wv.y, q1);
            q2 = fmaf(cf, wv.z, q2); q3 = fmaf(cf, wv.w, q3);
        }
        q0 += __shfl_xor_sync(FULLM, q0, 1);
        q1 += __shfl_xor_sync(FULLM, q1, 1);
        q2 += __shfl_xor_sync(FULLM, q2, 1);
        q3 += __shfl_xor_sync(FULLM, q3, 1);
        if (idx < 18 && half == 0) {
            Qn[k9][0]=q0; Qn[k9][1]=q1; Qn[k9][2]=q2; Qn[k9][3]=q3;
        }
    } else if (w >= 10 && w <= 12) {
        // QA cross term for perturbed atom A, one warp per mu
        const int mu = w - 10;
        float q0=0,q1=0,q2=0,q3=0;
        #pragma unroll
        for (int rep = 0; rep < 2; rep++) {
            int hh = lane + rep*32;
            if (hh < HIDDEN) {
                float ud = 0.f;
                #pragma unroll
                for (int k = 0; k < 9; k++)
                    ud = fmaf(wdd[mu][k], U1[k][hh], ud);
                float cf = f2a[A][hh] * ud * ud;
                float4 wv = *(const float4*)&W2s[hh][0];
                q0 = fmaf(cf, wv.x, q0); q1 = fmaf(cf, wv.y, q1);
                q2 = fmaf(cf, wv.z, q2); q3 = fmaf(cf, wv.w, q3);
            }
        }
        #pragma unroll
        for (int off = 16; off > 0; off >>= 1) {
            q0 += __shfl_xor_sync(FULLM, q0, off);
            q1 += __shfl_xor_sync(FULLM, q1, off);
            q2 += __shfl_xor_sync(FULLM, q2, off);
            q3 += __shfl_xor_sync(FULLM, q3, off);
        }
        if (lane == 0) { QA[mu][0]=q0; QA[mu][1]=q1; QA[mu][2]=q2; QA[mu][3]=q3; }
    }
    __syncthreads();

    // -------- P6: only warps 0-3 continue; the rest exit --------
    if (w >= 4) return;

    if (tid >= 96 && tid < 96 + NSTATES) {
        int s = tid - 96;
        float acc = 0.f;
        #pragma unroll
        for (int j = 0; j < NATOMS; j++)
            acc = fmaf(pv[j][s], Rr[j], acc);
        Tval[s] = acc;
    }
    if (w < 3) {
        const int mu = w;
        float accA = 0.f;
        if (lane < 8) {
            int s = lane & 3;
            bool second = lane >= 4;
            #pragma unroll
            for (int k = 0; k < 9; k++) {
                float dd = wdd[mu][k], dh = wdh[mu][k];
                accA += second ? fmaf(dd*dd, V2[k][s], dh*V1[k][s])
                               : dd*V1[k][s];
            }
        }
        if (lane < 4)      wpd[mu][A][lane]   = accA;
        else if (lane < 8) wph[mu][A][lane-4] = accA + QA[mu][lane-4];
        __syncwarp();

        #pragma unroll
        for (int base = 0; base < 36; base += 32) {
            int item = base + lane;
            if (item < 36) {
                int k9 = item >> 2, s = item & 3;
                int kk = 9 + k9;
                float dd = wdd[mu][kk], dh = wdh[mu][kk];
                float pd = dd * V1[kk][s];
                float ph = dd*dd*(V2[kk][s] + Qn[k9][s]) + dh*V1[kk][s];
                int at = jlA(k9, A);
                wpd[mu][at][s] = pd;
                wph[mu][at][s] = ph;
            }
        }
        __syncwarp();

        {
            int s = lane & 3, g = lane >> 2;
            float td = 0.f, th = 0.f;
            for (int k = g; k < 9; k += 8) {
                int j = jlA(k, A);
                float ddc = wdd[mu][k], dhc = wdh[mu][k];
                float rdc = rad1k[k]*ddc;
                float rhc = fmaf(rad2k[k], ddc*ddc, rad1k[k]*dhc);
                td = fmaf(pv[j][s], rdc, td);
                th = fmaf(2.f*wpd[mu][j][s], rdc, fmaf(pv[j][s], rhc, th));
                float ddn = wdd[mu][9+k], dhn = wdh[mu][9+k];
                float rdn = rad1k[9+k]*ddn;
                float rhn = fmaf(rad2k[9+k], ddn*ddn, rad1k[9+k]*dhn);
                td = fmaf(pv[A][s], rdn, td);
                th = fmaf(2.f*wpd[mu][A][s], rdn, fmaf(pv[A][s], rhn, th));
            }
            for (int at = g; at < NATOMS; at += 8) {
                td = fmaf(wpd[mu][at][s], Rr[at], td);
                th = fmaf(wph[mu][at][s], Rr[at], th);
            }
            #pragma unroll
            for (int off = 4; off < 32; off <<= 1) {
                td += __shfl_xor_sync(FULLM, td, off);
                th += __shfl_xor_sync(FULLM, th, off);
            }
            if (lane < 4) {
                Bsh[mu][lane] = td;
                Hsh[mu][lane] = th;
            }
        }
    }
    // named barrier over warps 0-3 only (128 threads)
    asm volatile("bar.sync 1, 128;" ::: "memory");

    // -------- P7: warp 0 only --------
    if (w != 0) return;
    if (tid < NSTATES) {
        int s = tid;
        float T0 = Tval[0];
        float acc = 0.f;
        #pragma unroll
        for (int mu = 0; mu < 3; mu++) {
            float Bv = Bsh[mu][s], Hv = Hsh[mu][s];
            acc += (s == 0) ? (2.f*Bv*Bv + 2.f*T0*Hv) : Hv;
        }
        // [c][s][a] layout: contiguous reads for the finalize lanes
        g_kin[(c*NSTATES + s)*NATOMS + A] = s_mass * acc;
        if (A == 0) g_T[c*NSTATES + s] = Tval[s];
    }
    __threadfence();           // publish g_kin/g_T (all lanes)
    __syncwarp();
    int flag = 0;
    if (lane == 0) {
        int old;
        asm volatile("atom.acq_rel.gpu.add.s32 %0, [%1], 1;"
                     : "=r"(old) : "l"(&g_fin) : "memory");
        flag = (old == NBLOCKS - 1);
    }
    flag = __shfl_sync(FULLM, flag, 0);
    if (!flag) return;
    // acquire from the atomic orders the reads below; pot is prefetched
    const int s = tid & 3;                   // lane = (config, state)
    const float2* gk2 = reinterpret_cast<const float2*>(g_kin + tid*NATOMS);
    float k0 = 0.f, k1 = 0.f;
    #pragma unroll
    for (int i = 0; i < 5; i++) {
        float2 v = gk2[i];
        k0 += v.x; k1 += v.y;
    }
    float kin = -0.5f * (k0 + k1);
    float Ts = g_T[tid];
    float T0 = __shfl_sync(FULLM, Ts, tid & ~3);
    float psi = (s == 0) ? T0*T0 : Ts;
    float pe  = potA - potLast;              // prefetched at P1
    float vib = (kin + psi*pe) / psi;
    float dvv = vib - s_el[s];
    float l = dvv*dvv;
    #pragma unroll
    for (int off = 16; off > 0; off >>= 1)
        l += __shfl_xor_sync(FULLM, l, off);
    if (tid == 0) {
        out[0] = l;
        g_fin = 0;   // reset for next graph replay
    }
}

extern "C" void kernel_launch(void* const* d_in, const int* in_sizes, int n_in,
                              void* d_out, int out_size)
{
    // metadata order: eigen_weight, pot, cart, numatoms, species, massrev,
    //                 atom_index, shifts, W1, B1, W2, Emb, elevel
    const float* pot     = (const float*)d_in[1];
    const float* cart    = (const float*)d_in[2];
    const int*   species = (const int*)  d_in[4];
    const float* massrev = (const float*)d_in[5];
    const float* W1      = (const float*)d_in[8];
    const float* B1      = (const float*)d_in[9];
    const float* W2      = (const float*)d_in[10];
    const float* Emb     = (const float*)d_in[11];
    const float* elevel  = (const float*)d_in[12];

    fused_kernel<<<NBLOCKS, NT>>>(pot, cart, species, massrev,
                                  W1, B1, W2, Emb, elevel, (float*)d_out);
}

// round 12
// speedup vs baseline: 1.2351x; 1.0208x over previous
#include <cuda_runtime.h>

#define NCONF   8
#define NATOMS  10
#define NSTATES 4
#define NBASIS  24
#define HIDDEN  48
#define NTYPES  4
#define PPC     90            // ordered pairs, contiguous: p = i*9 + (j - (j>i))
#define NT      512
#define NBLOCKS (NCONF*NATOMS)

#define PI_F 3.14159265358979323846f
#define CUT  6.0f
#define KARG (PI_F/CUT)
#define AL   1.5f
#define DLT  (CUT/23.0f)
#define FULLM 0xffffffffu

// cross-block scratch (no cudaMalloc allowed)
// kin accumulated by REDG atomicAdd per (config,state); zeroed by last block each launch
__device__ __align__(16) float g_kinCS[NCONF*NSTATES];
__device__ float g_T[NCONF*NSTATES];
__device__ int   g_fin;

__device__ __forceinline__ int jlA(int t, int A) { return t + (t >= A); }

__device__ __forceinline__ float fast_tanh(float u) {
    float ex = __expf(2.f*u);
    return 1.f - __fdividef(2.f, ex + 1.f);
}

__global__ void __launch_bounds__(NT, 1)
fused_kernel(const float* __restrict__ pot, const float* __restrict__ cart,
             const int* __restrict__ species, const float* __restrict__ massrev,
             const float* __restrict__ W1, const float* __restrict__ B1,
             const float* __restrict__ W2, const float* __restrict__ Emb,
             const float* __restrict__ elevel, float* __restrict__ out)
{
    __shared__ __align__(16) float W1s[NBASIS][52];
    __shared__ __align__(16) float W2s[HIDDEN][4];
    __shared__ float B1all[NTYPES][48];
    __shared__ float EmbAll[NTYPES][4];
    __shared__ int   s_sp[NATOMS];
    __shared__ float s_mass, s_el[4];
    __shared__ float G0[PPC][25];
    __shared__ float radv[PPC];
    __shared__ float G1k[18][25], G2k[18][25];
    __shared__ float rad1k[18], rad2k[18];
    __shared__ float wdd[3][18], wdh[3][18];
    __shared__ float densv[NATOMS][25];
    __shared__ float Rr[NATOMS];
    __shared__ float tval[NATOMS][49], f1a[NATOMS][49], f2a[NATOMS][49];
    __shared__ __align__(16) float U1[18][52], U2[18][52];
    __shared__ float pv[NATOMS][4];
    __shared__ float V1[18][4], V2[18][4], Qn[9][4];
    __shared__ float QA[3][4];
    __shared__ float wpd[3][NATOMS][4], wph[3][NATOMS][4];
    __shared__ float Tval[4];
    __shared__ float Bsh[3][4], Hsh[3][4];

    const int tid  = threadIdx.x;
    const int w    = tid >> 5;
    const int lane = tid & 31;
    const int c    = blockIdx.x / NATOMS;
    const int A    = blockIdx.x % NATOMS;
    const float* cb = cart + c*NATOMS*3;

    // prefetch pot for the finalize path (warp 0 only)
    float potA = 0.f, potLast = 0.f;
    if (w == 0) { potA = pot[lane >> 2]; potLast = pot[NCONF-1]; }

    // -------- P1+P2 merged: weight loads + pair geometry in one phase --------
    if (tid < PPC) {
        // pair threads load their own cart values directly from global
        const int p = tid;
        const int i = p / 9, jr = p % 9;
        const int j = jr + (jr >= i);
        float dx = cb[j*3+0] - cb[i*3+0];
        float dy = cb[j*3+1] - cb[i*3+1];
        float dz = cb[j*3+2] - cb[i*3+2];
        float d2 = fmaf(dx, dx, fmaf(dy, dy, dz*dz));
        float d  = sqrtf(d2);
        float arg = d * KARG;
        float sn = __sinf(arg), cs = __cosf(arg);
        radv[p] = sn*sn*sn;
        float f0 = (d < CUT) ? 0.5f*(cs + 1.f) : 0.f;

        // rbf via 4 independent 6-step recurrences
        const float gg = __expf(-2.f*AL*DLT*DLT);
        float gg2 = gg*gg, gg3 = gg2*gg, gg6 = gg3*gg3;
        float tc = __expf(fmaf(2.f*AL*DLT, d, -AL*DLT*DLT));
        float t0 = tc, t1 = tc*gg6, t2 = t1*gg6, t3 = t2*gg6;
        float rb0  = __expf(-AL*d2);
        float d6   = d -  6.f*DLT; float rb6  = __expf(-AL*d6*d6);
        float d12  = d - 12.f*DLT; float rb12 = __expf(-AL*d12*d12);
        float d18  = d - 18.f*DLT; float rb18 = __expf(-AL*d18*d18);
        #pragma unroll
        for (int i2 = 0; i2 < 6; i2++) {
            G0[p][i2]      = rb0 *f0;
            G0[p][6 + i2]  = rb6 *f0;
            G0[p][12 + i2] = rb12*f0;
            G0[p][18 + i2] = rb18*f0;
            rb0 *= t0; rb6 *= t1; rb12 *= t2; rb18 *= t3;
            t0 *= gg; t1 *= gg; t2 *= gg; t3 *= gg;
        }
    } else if (tid >= 96 && tid < 96 + 36) {
        // A-pair jets: (k, bhalf) split, 36 threads, direct cart loads
        const int idx = tid - 96;
        const int k     = idx >> 1;
        const int bhalf = idx & 1;
        const int b0    = bhalf * 12;
        const bool isC = (k < 9);
        const int i = isC ? A : jlA(k - 9, A);
        const int j = isC ? jlA(k, A) : A;
        float dx = cb[j*3+0] - cb[i*3+0];
        float dy = cb[j*3+1] - cb[i*3+1];
        float dz = cb[j*3+2] - cb[i*3+2];
        float d2 = fmaf(dx, dx, fmaf(dy, dy, dz*dz));
        float d  = sqrtf(d2);
        float arg = d * KARG;
        float sn = __sinf(arg), cs = __cosf(arg);
        float f0, fd1, fd2;
        if (d < CUT) {
            f0  = 0.5f*(cs + 1.f);
            fd1 = -0.5f*KARG*sn;
            fd2 = -0.5f*KARG*KARG*cs;
        } else { f0 = 0.f; fd1 = 0.f; fd2 = 0.f; }
        if (bhalf == 0) {
            rad1k[k] = 3.f*sn*sn*cs * KARG;
            rad2k[k] = (6.f*sn*cs*cs - 3.f*sn*sn*sn) * (KARG*KARG);
            float invd = __frcp_rn(d);
            float sgn = isC ? -1.f : 1.f;
            float ex = dx*invd, ey = dy*invd, ez = dz*invd;
            wdd[0][k] = sgn*ex; wdh[0][k] = (1.f - ex*ex)*invd;
            wdd[1][k] = sgn*ey; wdh[1][k] = (1.f - ey*ey)*invd;
            wdd[2][k] = sgn*ez; wdh[2][k] = (1.f - ez*ez)*invd;
        }
        const float gg = __expf(-2.f*AL*DLT*DLT);
        float gg2 = gg*gg, gg3 = gg2*gg, gg6 = gg3*gg3;
        float tc  = __expf(fmaf(2.f*AL*DLT, d, -AL*DLT*DLT));
        float ggb = bhalf ? gg6*gg6 : 1.f;
        float ta = tc * ggb;
        float tb = ta * gg6;
        float da  = d - (float)b0*DLT;      float rba = __expf(-AL*da*da);
        float db_ = d - (float)(b0+6)*DLT;  float rbb = __expf(-AL*db_*db_);
        #pragma unroll
        for (int i2 = 0; i2 < 6; i2++) {
            int ba = b0 + i2, bb = b0 + 6 + i2;
            float t_a = d - (float)ba*DLT;
            float r1a = -2.f*AL*t_a*rba;
            float r2a = (4.f*AL*AL*t_a*t_a - 2.f*AL)*rba;
            G1k[k][ba] = r1a*f0 + rba*fd1;
            G2k[k][ba] = r2a*f0 + 2.f*r1a*fd1 + rba*fd2;
            float t_b = d - (float)bb*DLT;
            float r1b = -2.f*AL*t_b*rbb;
            float r2b = (4.f*AL*AL*t_b*t_b - 2.f*AL)*rbb;
            G1k[k][bb] = r1b*f0 + rbb*fd1;
            G2k[k][bb] = r2b*f0 + 2.f*r1b*fd1 + rbb*fd2;
            rba *= ta; rbb *= tb; ta *= gg; tb *= gg;
        }
    } else if (tid >= 160 && tid < 160 + 192) {
        // weight loads: W1 (1152 floats) on 192 threads (6 each)
        const int base = tid - 160;
        #pragma unroll
        for (int r = 0; r < 6; r++) {
            int i = base + r*192;
            W1s[i / HIDDEN][i % HIDDEN] = W1[i];
        }
    } else if (tid >= 352 && tid < 352 + 48) {
        // W2 (192) on 48 threads (4 each) — strided for coalescing
        const int base = tid - 352;
        #pragma unroll
        for (int r = 0; r < 4; r++) {
            int i = base + r*48;
            W2s[i >> 2][i & 3] = W2[i];
        }
    } else if (tid >= 400 && tid < 400 + 48) {
        // B1 all species (192) on 48 threads
        const int base = tid - 400;
        #pragma unroll
        for (int r = 0; r < 4; r++) {
            int i = base + r*48;
            B1all[i / 48][i % 48] = B1[i];
        }
    } else if (tid >= 448 && tid < 448 + 16) {
        int i = tid - 448;
        EmbAll[i >> 2][i & 3] = Emb[i];
    } else if (tid >= 464 && tid < 464 + NATOMS) {
        s_sp[tid - 464] = species[c*NATOMS + (tid - 464)];
    } else if (tid == 474) {
        s_mass = massrev[c*NATOMS + A];
    } else if (tid >= 476 && tid < 476 + NSTATES) {
        s_el[tid - 476] = elevel[tid - 476];
    }
    __syncthreads();

    // -------- P3: U1/U2 (b-split, 432 threads) + densv/Rr (warps 14-15) --------
    if (tid < 448) {
        const int idx = tid;
        const bool valid = idx < 432;
        int k  = idx / 24; if (k > 17) k = 17;
        const int rem = idx % 24;
        const int hq = (rem >> 1) * 4;
        const int bhalf = rem & 1;
        const int b0 = bhalf * 12;
        float a0=0,a1=0,a2=0,a3=0, c0=0,c1=0,c2=0,c3=0;
        #pragma unroll
        for (int bi = 0; bi < 12; bi++) {
            int b = b0 + bi;
            float g1 = G1k[k][b], g2 = G2k[k][b];
            float4 wv = *(const float4*)&W1s[b][hq];
            a0 = fmaf(g1, wv.x, a0); a1 = fmaf(g1, wv.y, a1);
            a2 = fmaf(g1, wv.z, a2); a3 = fmaf(g1, wv.w, a3);
            c0 = fmaf(g2, wv.x, c0); c1 = fmaf(g2, wv.y, c1);
            c2 = fmaf(g2, wv.z, c2); c3 = fmaf(g2, wv.w, c3);
        }
        a0 += __shfl_xor_sync(FULLM, a0, 1);
        a1 += __shfl_xor_sync(FULLM, a1, 1);
        a2 += __shfl_xor_sync(FULLM, a2, 1);
        a3 += __shfl_xor_sync(FULLM, a3, 1);
        c0 += __shfl_xor_sync(FULLM, c0, 1);
        c1 += __shfl_xor_sync(FULLM, c1, 1);
        c2 += __shfl_xor_sync(FULLM, c2, 1);
        c3 += __shfl_xor_sync(FULLM, c3, 1);
        if (valid && bhalf == 0) {
            U1[k][hq]=a0; U1[k][hq+1]=a1; U1[k][hq+2]=a2; U1[k][hq+3]=a3;
            U2[k][hq]=c0; U2[k][hq+1]=c1; U2[k][hq+2]=c2; U2[k][hq+3]=c3;
        }
    } else {
        for (int item = tid - 448; item < NATOMS*NBASIS + NATOMS; item += 64) {
            if (item < NATOMS*NBASIS) {
                int at = item / NBASIS, b = item % NBASIS;
                float a0 = 0.f, a1 = 0.f;
                #pragma unroll
                for (int r = 0; r < 8; r += 2) {
                    a0 += G0[at*9 + r][b];
                    a1 += G0[at*9 + r + 1][b];
                }
                densv[at][b] = a0 + a1 + G0[at*9 + 8][b];
            } else {
                int at = item - NATOMS*NBASIS;
                float r = 0.f;
                #pragma unroll
                for (int j = 0; j < NATOMS; j++)
                    if (j != at) r += radv[j*9 + (at - (at > j))];
                Rr[at] = r;
            }
        }
    }
    __syncthreads();

    // -------- P4: tanh value path, 1 item per thread --------
    if (tid < NATOMS*HIDDEN) {
        int at = tid / HIDDEN, hh = tid % HIDDEN;
        float u0 = B1all[s_sp[at]][hh], u1 = 0.f, u2 = 0.f, u3 = 0.f;
        #pragma unroll
        for (int b = 0; b < NBASIS; b += 4) {
            u0 = fmaf(densv[at][b  ], W1s[b  ][hh], u0);
            u1 = fmaf(densv[at][b+1], W1s[b+1][hh], u1);
            u2 = fmaf(densv[at][b+2], W1s[b+2][hh], u2);
            u3 = fmaf(densv[at][b+3], W1s[b+3][hh], u3);
        }
        float t  = fast_tanh((u0 + u1) + (u2 + u3));
        float f1 = 1.f - t*t;
        tval[at][hh] = t;
        f1a[at][hh]  = f1;
        f2a[at][hh]  = -2.f*t*f1;
    }
    __syncthreads();

    // -------- P5: pv (hh-halves), V1/V2 (hh-quarters), Qn (hh-halves), QA --------
    if (w < 3) {
        const bool valid = tid < 80;
        int at = tid >> 3; if (at > 9) at = 9;
        const int s = (tid >> 1) & 3;
        const int half = tid & 1;
        const int h0 = half * 24;
        float a0 = 0.f, a1 = 0.f;
        #pragma unroll
        for (int hi = 0; hi < 24; hi += 2) {
            a0 = fmaf(tval[at][h0+hi  ], W2s[h0+hi  ][s], a0);
            a1 = fmaf(tval[at][h0+hi+1], W2s[h0+hi+1][s], a1);
        }
        float v = a0 + a1;
        v += __shfl_xor_sync(FULLM, v, 1);
        if (valid && half == 0) pv[at][s] = v + EmbAll[s_sp[at]][s];
    } else if (w >= 4 && w <= 8) {
        const int idx = tid - 128;
        const bool valid = idx < 144;
        int k = idx >> 3; if (k > 17) k = 17;
        const int which = (idx >> 2) & 1;
        const int quarter = idx & 3;
        const int cen = (k < 9) ? A : jlA(k - 9, A);
        const int h0 = quarter * 12;
        float v0=0,v1=0,v2=0,v3=0;
        #pragma unroll
        for (int hi = 0; hi < 12; hi++) {
            int hh = h0 + hi;
            float u = (which ? U2[k][hh] : U1[k][hh]) * f1a[cen][hh];
            float4 wv = *(const float4*)&W2s[hh][0];
            v0 = fmaf(u, wv.x, v0); v1 = fmaf(u, wv.y, v1);
            v2 = fmaf(u, wv.z, v2); v3 = fmaf(u, wv.w, v3);
        }
        #pragma unroll
        for (int off = 1; off <= 2; off <<= 1) {
            v0 += __shfl_xor_sync(FULLM, v0, off);
            v1 += __shfl_xor_sync(FULLM, v1, off);
            v2 += __shfl_xor_sync(FULLM, v2, off);
            v3 += __shfl_xor_sync(FULLM, v3, off);
        }
        if (valid && quarter == 0) {
            if (which) { V2[k][0]=v0; V2[k][1]=v1; V2[k][2]=v2; V2[k][3]=v3; }
            else       { V1[k][0]=v0; V1[k][1]=v1; V1[k][2]=v2; V1[k][3]=v3; }
        }
    } else if (w == 9) {
        // Qn: (k9, half) = 18 items on one warp; lanes 18-31 padded (no write)
        const int idx = lane;
        int k9 = idx >> 1; if (k9 > 8) k9 = 8;
        const int half = idx & 1;
        const int cen = jlA(k9, A);
        const int h0 = half * 24;
        float q0=0,q1=0,q2=0,q3=0;
        #pragma unroll
        for (int hi = 0; hi < 24; hi++) {
            int hh = h0 + hi;
            float u = U1[9+k9][hh];
            float cf = f2a[cen][hh] * u * u;
            float4 wv = *(const float4*)&W2s[hh][0];
            q0 = fmaf(cf, wv.x, q0); q1 = fmaf(cf, wv.y, q1);
            q2 = fmaf(cf, wv.z, q2); q3 = fmaf(cf, wv.w, q3);
        }
        q0 += __shfl_xor_sync(FULLM, q0, 1);
        q1 += __shfl_xor_sync(FULLM, q1, 1);
        q2 += __shfl_xor_sync(FULLM, q2, 1);
        q3 += __shfl_xor_sync(FULLM, q3, 1);
        if (idx < 18 && half == 0) {
            Qn[k9][0]=q0; Qn[k9][1]=q1; Qn[k9][2]=q2; Qn[k9][3]=q3;
        }
    } else if (w >= 10 && w <= 12) {
        const int mu = w - 10;
        float q0=0,q1=0,q2=0,q3=0;
        #pragma unroll
        for (int rep = 0; rep < 2; rep++) {
            int hh = lane + rep*32;
            if (hh < HIDDEN) {
                float ud = 0.f;
                #pragma unroll
                for (int k = 0; k < 9; k++)
                    ud = fmaf(wdd[mu][k], U1[k][hh], ud);
                float cf = f2a[A][hh] * ud * ud;
                float4 wv = *(const float4*)&W2s[hh][0];
                q0 = fmaf(cf, wv.x, q0); q1 = fmaf(cf, wv.y, q1);
                q2 = fmaf(cf, wv.z, q2); q3 = fmaf(cf, wv.w, q3);
            }
        }
        #pragma unroll
        for (int off = 16; off > 0; off >>= 1) {
            q0 += __shfl_xor_sync(FULLM, q0, off);
            q1 += __shfl_xor_sync(FULLM, q1, off);
            q2 += __shfl_xor_sync(FULLM, q2, off);
            q3 += __shfl_xor_sync(FULLM, q3, off);
        }
        if (lane == 0) { QA[mu][0]=q0; QA[mu][1]=q1; QA[mu][2]=q2; QA[mu][3]=q3; }
    }
    __syncthreads();

    // -------- P6: only warps 0-3 continue; the rest exit --------
    if (w >= 4) return;

    if (tid >= 96 && tid < 96 + NSTATES) {
        int s = tid - 96;
        float acc = 0.f;
        #pragma unroll
        for (int j = 0; j < NATOMS; j++)
            acc = fmaf(pv[j][s], Rr[j], acc);
        Tval[s] = acc;
    }
    if (w < 3) {
        const int mu = w;
        float accA = 0.f;
        if (lane < 8) {
            int s = lane & 3;
            bool second = lane >= 4;
            #pragma unroll
            for (int k = 0; k < 9; k++) {
                float dd = wdd[mu][k], dh = wdh[mu][k];
                accA += second ? fmaf(dd*dd, V2[k][s], dh*V1[k][s])
                               : dd*V1[k][s];
            }
        }
        if (lane < 4)      wpd[mu][A][lane]   = accA;
        else if (lane < 8) wph[mu][A][lane-4] = accA + QA[mu][lane-4];
        __syncwarp();

        #pragma unroll
        for (int base = 0; base < 36; base += 32) {
            int item = base + lane;
            if (item < 36) {
                int k9 = item >> 2, s = item & 3;
                int kk = 9 + k9;
                float dd = wdd[mu][kk], dh = wdh[mu][kk];
                float pd = dd * V1[kk][s];
                float ph = dd*dd*(V2[kk][s] + Qn[k9][s]) + dh*V1[kk][s];
                int at = jlA(k9, A);
                wpd[mu][at][s] = pd;
                wph[mu][at][s] = ph;
            }
        }
        __syncwarp();

        {
            int s = lane & 3, g = lane >> 2;
            float td = 0.f, th = 0.f;
            for (int k = g; k < 9; k += 8) {
                int j = jlA(k, A);
                float ddc = wdd[mu][k], dhc = wdh[mu][k];
                float rdc = rad1k[k]*ddc;
                float rhc = fmaf(rad2k[k], ddc*ddc, rad1k[k]*dhc);
                td = fmaf(pv[j][s], rdc, td);
                th = fmaf(2.f*wpd[mu][j][s], rdc, fmaf(pv[j][s], rhc, th));
                float ddn = wdd[mu][9+k], dhn = wdh[mu][9+k];
                float rdn = rad1k[9+k]*ddn;
                float rhn = fmaf(rad2k[9+k], ddn*ddn, rad1k[9+k]*dhn);
                td = fmaf(pv[A][s], rdn, td);
                th = fmaf(2.f*wpd[mu][A][s], rdn, fmaf(pv[A][s], rhn, th));
            }
            for (int at = g; at < NATOMS; at += 8) {
                td = fmaf(wpd[mu][at][s], Rr[at], td);
                th = fmaf(wph[mu][at][s], Rr[at], th);
            }
            #pragma unroll
            for (int off = 4; off < 32; off <<= 1) {
                td += __shfl_xor_sync(FULLM, td, off);
                th += __shfl_xor_sync(FULLM, th, off);
            }
            if (lane < 4) {
                Bsh[mu][lane] = td;
                Hsh[mu][lane] = th;
            }
        }
    }
    // named barrier over warps 0-3 only (128 threads)
    asm volatile("bar.sync 1, 128;" ::: "memory");

    // -------- P7: warp 0 only --------
    if (w != 0) return;
    if (tid < NSTATES) {
        int s = tid;
        float T0 = Tval[0];
        float acc = 0.f;
        #pragma unroll
        for (int mu = 0; mu < 3; mu++) {
            float Bv = Bsh[mu][s], Hv = Hsh[mu][s];
            acc += (s == 0) ? (2.f*Bv*Bv + 2.f*T0*Hv) : Hv;
        }
        atomicAdd(&g_kinCS[c*NSTATES + s], s_mass * acc);   // REDG, no return
        if (A == 0) g_T[c*NSTATES + s] = Tval[s];
    }
    __threadfence();           // publish REDG + g_T before the counter
    __syncwarp();
    int flag = 0;
    if (lane == 0) {
        int old;
        asm volatile("atom.acq_rel.gpu.add.s32 %0, [%1], 1;"
                     : "=r"(old) : "l"(&g_fin) : "memory");
        flag = (old == NBLOCKS - 1);
    }
    flag = __shfl_sync(FULLM, flag, 0);
    if (!flag) return;
    // last block: lane = (config, state); 32 contiguous accumulators
    const int s = tid & 3;
    float kin = -0.5f * g_kinCS[tid];
    float Ts = g_T[tid];
    g_kinCS[tid] = 0.f;                      // reset for next graph replay
    float T0 = __shfl_sync(FULLM, Ts, tid & ~3);
    float psi = (s == 0) ? T0*T0 : Ts;
    float pe  = potA - potLast;              // prefetched at P1
    float vib = (kin + psi*pe) / psi;
    float dvv = vib - s_el[s];
    float l = dvv*dvv;
    #pragma unroll
    for (int off = 16; off > 0; off >>= 1)
        l += __shfl_xor_sync(FULLM, l, off);
    if (tid == 0) {
        out[0] = l;
        g_fin = 0;   // reset for next graph replay
    }
}

extern "C" void kernel_launch(void* const* d_in, const int* in_sizes, int n_in,
                              void* d_out, int out_size)
{
    // metadata order: eigen_weight, pot, cart, numatoms, species, massrev,
    //                 atom_index, shifts, W1, B1, W2, Emb, elevel
    const float* pot     = (const float*)d_in[1];
    const float* cart    = (const float*)d_in[2];
    const int*   species = (const int*)  d_in[4];
    const float* massrev = (const float*)d_in[5];
    const float* W1      = (const float*)d_in[8];
    const float* B1      = (const float*)d_in[9];
    const float* W2      = (const float*)d_in[10];
    const float* Emb     = (const float*)d_in[11];
    const float* elevel  = (const float*)d_in[12];

    fused_kernel<<<NBLOCKS, NT>>>(pot, cart, species, massrev,
                                  W1, B1, W2, Emb, elevel, (float*)d_out);
}

// round 13
// speedup vs baseline: 1.2388x; 1.0030x over previous
#include <cuda_runtime.h>

#define NCONF   8
#define NATOMS  10
#define NSTATES 4
#define NBASIS  24
#define HIDDEN  48
#define NTYPES  4
#define PPC     90            // ordered pairs, contiguous: p = i*9 + (j - (j>i))
#define NT      1024
#define NBLOCKS (NCONF*NATOMS)

#define PI_F 3.14159265358979323846f
#define CUT  6.0f
#define KARG (PI_F/CUT)
#define AL   1.5f
#define DLT  (CUT/23.0f)
#define FULLM 0xffffffffu

// cross-block scratch (no cudaMalloc allowed)
__device__ __align__(16) float g_kinCS[NCONF*NSTATES];
__device__ float g_T[NCONF*NSTATES];
__device__ int   g_fin;

__device__ __forceinline__ int jlA(int t, int A) { return t + (t >= A); }

__device__ __forceinline__ float fast_tanh(float u) {
    float ex = __expf(2.f*u);
    return 1.f - __fdividef(2.f, ex + 1.f);
}

__global__ void __launch_bounds__(NT, 1)
fused_kernel(const float* __restrict__ pot, const float* __restrict__ cart,
             const int* __restrict__ species, const float* __restrict__ massrev,
             const float* __restrict__ W1, const float* __restrict__ B1,
             const float* __restrict__ W2, const float* __restrict__ Emb,
             const float* __restrict__ elevel, float* __restrict__ out)
{
    __shared__ __align__(16) float W1s[NBASIS][52];
    __shared__ __align__(16) float W2s[HIDDEN][4];
    __shared__ float B1all[NTYPES][48];
    __shared__ float EmbAll[NTYPES][4];
    __shared__ int   s_sp[NATOMS];
    __shared__ float s_mass, s_el[4];
    __shared__ float G0[PPC][25];
    __shared__ float radv[PPC];
    __shared__ float G1k[18][25], G2k[18][25];
    __shared__ float rad1k[18], rad2k[18];
    __shared__ float wdd[3][18], wdh[3][18];
    __shared__ float Rr[NATOMS];
    __shared__ float tval[NATOMS][49], f1a[NATOMS][49], f2a[NATOMS][49];
    __shared__ __align__(16) float U1[18][52], U2[18][52];
    __shared__ float pv[NATOMS][4];
    __shared__ float V1[18][4], V2[18][4], Qn[9][4];
    __shared__ float QA[3][4];
    __shared__ float wpd[3][NATOMS][4], wph[3][NATOMS][4];
    __shared__ float Tval[4];
    __shared__ float Bsh[3][4], Hsh[3][4];

    const int tid  = threadIdx.x;
    const int w    = tid >> 5;
    const int lane = tid & 31;
    const int c    = blockIdx.x / NATOMS;
    const int A    = blockIdx.x % NATOMS;
    const float* cb = cart + c*NATOMS*3;

    // prefetch pot for the finalize path (warp 0 only)
    float potA = 0.f, potLast = 0.f;
    if (w == 0) { potA = pot[lane >> 2]; potLast = pot[NCONF-1]; }

    // -------- Phase A: weight loads + pair geometry, one phase --------
    if (tid < PPC) {
        const int p = tid;
        const int i = p / 9, jr = p % 9;
        const int j = jr + (jr >= i);
        float dx = cb[j*3+0] - cb[i*3+0];
        float dy = cb[j*3+1] - cb[i*3+1];
        float dz = cb[j*3+2] - cb[i*3+2];
        float d2 = fmaf(dx, dx, fmaf(dy, dy, dz*dz));
        float d  = sqrtf(d2);
        float arg = d * KARG;
        float sn = __sinf(arg), cs = __cosf(arg);
        radv[p] = sn*sn*sn;
        float f0 = (d < CUT) ? 0.5f*(cs + 1.f) : 0.f;

        const float gg = __expf(-2.f*AL*DLT*DLT);
        float gg2 = gg*gg, gg3 = gg2*gg, gg6 = gg3*gg3;
        float tc = __expf(fmaf(2.f*AL*DLT, d, -AL*DLT*DLT));
        float t0 = tc, t1 = tc*gg6, t2 = t1*gg6, t3 = t2*gg6;
        float rb0  = __expf(-AL*d2);
        float d6   = d -  6.f*DLT; float rb6  = __expf(-AL*d6*d6);
        float d12  = d - 12.f*DLT; float rb12 = __expf(-AL*d12*d12);
        float d18  = d - 18.f*DLT; float rb18 = __expf(-AL*d18*d18);
        #pragma unroll
        for (int i2 = 0; i2 < 6; i2++) {
            G0[p][i2]      = rb0 *f0;
            G0[p][6 + i2]  = rb6 *f0;
            G0[p][12 + i2] = rb12*f0;
            G0[p][18 + i2] = rb18*f0;
            rb0 *= t0; rb6 *= t1; rb12 *= t2; rb18 *= t3;
            t0 *= gg; t1 *= gg; t2 *= gg; t3 *= gg;
        }
    } else if (tid >= 96 && tid < 96 + 36) {
        // A-pair jets: (k, bhalf) split, 36 threads, direct cart loads
        const int idx = tid - 96;
        const int k     = idx >> 1;
        const int bhalf = idx & 1;
        const int b0    = bhalf * 12;
        const bool isC = (k < 9);
        const int i = isC ? A : jlA(k - 9, A);
        const int j = isC ? jlA(k, A) : A;
        float dx = cb[j*3+0] - cb[i*3+0];
        float dy = cb[j*3+1] - cb[i*3+1];
        float dz = cb[j*3+2] - cb[i*3+2];
        float d2 = fmaf(dx, dx, fmaf(dy, dy, dz*dz));
        float d  = sqrtf(d2);
        float arg = d * KARG;
        float sn = __sinf(arg), cs = __cosf(arg);
        float f0, fd1, fd2;
        if (d < CUT) {
            f0  = 0.5f*(cs + 1.f);
            fd1 = -0.5f*KARG*sn;
            fd2 = -0.5f*KARG*KARG*cs;
        } else { f0 = 0.f; fd1 = 0.f; fd2 = 0.f; }
        if (bhalf == 0) {
            rad1k[k] = 3.f*sn*sn*cs * KARG;
            rad2k[k] = (6.f*sn*cs*cs - 3.f*sn*sn*sn) * (KARG*KARG);
            float invd = __frcp_rn(d);
            float sgn = isC ? -1.f : 1.f;
            float ex = dx*invd, ey = dy*invd, ez = dz*invd;
            wdd[0][k] = sgn*ex; wdh[0][k] = (1.f - ex*ex)*invd;
            wdd[1][k] = sgn*ey; wdh[1][k] = (1.f - ey*ey)*invd;
            wdd[2][k] = sgn*ez; wdh[2][k] = (1.f - ez*ez)*invd;
        }
        const float gg = __expf(-2.f*AL*DLT*DLT);
        float gg2 = gg*gg, gg3 = gg2*gg, gg6 = gg3*gg3;
        float tc  = __expf(fmaf(2.f*AL*DLT, d, -AL*DLT*DLT));
        float ggb = bhalf ? gg6*gg6 : 1.f;
        float ta = tc * ggb;
        float tb = ta * gg6;
        float da  = d - (float)b0*DLT;      float rba = __expf(-AL*da*da);
        float db_ = d - (float)(b0+6)*DLT;  float rbb = __expf(-AL*db_*db_);
        #pragma unroll
        for (int i2 = 0; i2 < 6; i2++) {
            int ba = b0 + i2, bb = b0 + 6 + i2;
            float t_a = d - (float)ba*DLT;
            float r1a = -2.f*AL*t_a*rba;
            float r2a = (4.f*AL*AL*t_a*t_a - 2.f*AL)*rba;
            G1k[k][ba] = r1a*f0 + rba*fd1;
            G2k[k][ba] = r2a*f0 + 2.f*r1a*fd1 + rba*fd2;
            float t_b = d - (float)bb*DLT;
            float r1b = -2.f*AL*t_b*rbb;
            float r2b = (4.f*AL*AL*t_b*t_b - 2.f*AL)*rbb;
            G1k[k][bb] = r1b*f0 + rbb*fd1;
            G2k[k][bb] = r2b*f0 + 2.f*r1b*fd1 + rbb*fd2;
            rba *= ta; rbb *= tb; ta *= gg; tb *= gg;
        }
    } else if (tid >= 160 && tid < 160 + 384) {
        // W1 (1152 floats) on 384 threads (3 each)
        const int base = tid - 160;
        #pragma unroll
        for (int r = 0; r < 3; r++) {
            int i = base + r*384;
            W1s[i / HIDDEN][i % HIDDEN] = W1[i];
        }
    } else if (tid >= 544 && tid < 544 + 48) {
        const int base = tid - 544;
        #pragma unroll
        for (int r = 0; r < 4; r++) {
            int i = base + r*48;
            W2s[i >> 2][i & 3] = W2[i];
        }
    } else if (tid >= 592 && tid < 592 + 48) {
        const int base = tid - 592;
        #pragma unroll
        for (int r = 0; r < 4; r++) {
            int i = base + r*48;
            B1all[i / 48][i % 48] = B1[i];
        }
    } else if (tid >= 640 && tid < 640 + 16) {
        int i = tid - 640;
        EmbAll[i >> 2][i & 3] = Emb[i];
    } else if (tid >= 656 && tid < 656 + NATOMS) {
        s_sp[tid - 656] = species[c*NATOMS + (tid - 656)];
    } else if (tid == 666) {
        s_mass = massrev[c*NATOMS + A];
    } else if (tid >= 668 && tid < 668 + NSTATES) {
        s_el[tid - 668] = elevel[tid - 668];
    }
    __syncthreads();

    // -------- Phase B: U1/U2 + tanh (inline shfl-densv) + Rr, one phase --------
    if (tid < 448) {
        const int idx = tid;
        const bool valid = idx < 432;
        int k  = idx / 24; if (k > 17) k = 17;
        const int rem = idx % 24;
        const int hq = (rem >> 1) * 4;
        const int bhalf = rem & 1;
        const int b0 = bhalf * 12;
        float a0=0,a1=0,a2=0,a3=0, c0=0,c1=0,c2=0,c3=0;
        #pragma unroll
        for (int bi = 0; bi < 12; bi++) {
            int b = b0 + bi;
            float g1 = G1k[k][b], g2 = G2k[k][b];
            float4 wv = *(const float4*)&W1s[b][hq];
            a0 = fmaf(g1, wv.x, a0); a1 = fmaf(g1, wv.y, a1);
            a2 = fmaf(g1, wv.z, a2); a3 = fmaf(g1, wv.w, a3);
            c0 = fmaf(g2, wv.x, c0); c1 = fmaf(g2, wv.y, c1);
            c2 = fmaf(g2, wv.z, c2); c3 = fmaf(g2, wv.w, c3);
        }
        a0 += __shfl_xor_sync(FULLM, a0, 1);
        a1 += __shfl_xor_sync(FULLM, a1, 1);
        a2 += __shfl_xor_sync(FULLM, a2, 1);
        a3 += __shfl_xor_sync(FULLM, a3, 1);
        c0 += __shfl_xor_sync(FULLM, c0, 1);
        c1 += __shfl_xor_sync(FULLM, c1, 1);
        c2 += __shfl_xor_sync(FULLM, c2, 1);
        c3 += __shfl_xor_sync(FULLM, c3, 1);
        if (valid && bhalf == 0) {
            U1[k][hq]=a0; U1[k][hq+1]=a1; U1[k][hq+2]=a2; U1[k][hq+3]=a3;
            U2[k][hq]=c0; U2[k][hq+1]=c1; U2[k][hq+2]=c2; U2[k][hq+3]=c3;
        }
    } else if (w >= 14 && w < 14 + NATOMS) {
        // tanh path: warp = atom; lanes 0-23 own densv elements, shfl-broadcast
        const int at = w - 14;
        float dens = 0.f;
        if (lane < NBASIS) {
            float e0 = 0.f, e1 = 0.f;
            #pragma unroll
            for (int r = 0; r < 8; r += 2) {
                e0 += G0[at*9 + r][lane];
                e1 += G0[at*9 + r + 1][lane];
            }
            dens = e0 + e1 + G0[at*9 + 8][lane];
        }
        const int sp  = s_sp[at];
        const int hh1 = lane;               // 0..31
        const int hh2 = 32 + (lane & 15);   // lanes 0..15 write
        float uA0 = B1all[sp][hh1], uA1 = 0.f;
        float uB0 = B1all[sp][hh2], uB1 = 0.f;
        #pragma unroll
        for (int b = 0; b < NBASIS; b += 2) {
            float d0 = __shfl_sync(FULLM, dens, b);
            float d1 = __shfl_sync(FULLM, dens, b+1);
            uA0 = fmaf(d0, W1s[b  ][hh1], uA0);
            uA1 = fmaf(d1, W1s[b+1][hh1], uA1);
            uB0 = fmaf(d0, W1s[b  ][hh2], uB0);
            uB1 = fmaf(d1, W1s[b+1][hh2], uB1);
        }
        {
            float t1 = fast_tanh(uA0 + uA1);
            float f1 = 1.f - t1*t1;
            tval[at][hh1] = t1;
            f1a[at][hh1]  = f1;
            f2a[at][hh1]  = -2.f*t1*f1;
        }
        if (lane < 16) {
            float t2 = fast_tanh(uB0 + uB1);
            float f1 = 1.f - t2*t2;
            tval[at][hh2] = t2;
            f1a[at][hh2]  = f1;
            f2a[at][hh2]  = -2.f*t2*f1;
        }
    } else if (w == 24) {
        if (lane < NATOMS) {
            float r = 0.f;
            #pragma unroll
            for (int j = 0; j < NATOMS; j++)
                if (j != lane) r += radv[j*9 + (lane - (lane > j))];
            Rr[lane] = r;
        }
    }
    __syncthreads();

    // -------- Phase C (P5): pv, V1/V2, Qn, QA --------
    if (w < 3) {
        const bool valid = tid < 80;
        int at = tid >> 3; if (at > 9) at = 9;
        const int s = (tid >> 1) & 3;
        const int half = tid & 1;
        const int h0 = half * 24;
        float a0 = 0.f, a1 = 0.f;
        #pragma unroll
        for (int hi = 0; hi < 24; hi += 2) {
            a0 = fmaf(tval[at][h0+hi  ], W2s[h0+hi  ][s], a0);
            a1 = fmaf(tval[at][h0+hi+1], W2s[h0+hi+1][s], a1);
        }
        float v = a0 + a1;
        v += __shfl_xor_sync(FULLM, v, 1);
        if (valid && half == 0) pv[at][s] = v + EmbAll[s_sp[at]][s];
    } else if (w >= 4 && w <= 8) {
        const int idx = tid - 128;
        const bool valid = idx < 144;
        int k = idx >> 3; if (k > 17) k = 17;
        const int which = (idx >> 2) & 1;
        const int quarter = idx & 3;
        const int cen = (k < 9) ? A : jlA(k - 9, A);
        const int h0 = quarter * 12;
        float v0=0,v1=0,v2=0,v3=0;
        #pragma unroll
        for (int hi = 0; hi < 12; hi++) {
            int hh = h0 + hi;
            float u = (which ? U2[k][hh] : U1[k][hh]) * f1a[cen][hh];
            float4 wv = *(const float4*)&W2s[hh][0];
            v0 = fmaf(u, wv.x, v0); v1 = fmaf(u, wv.y, v1);
            v2 = fmaf(u, wv.z, v2); v3 = fmaf(u, wv.w, v3);
        }
        #pragma unroll
        for (int off = 1; off <= 2; off <<= 1) {
            v0 += __shfl_xor_sync(FULLM, v0, off);
            v1 += __shfl_xor_sync(FULLM, v1, off);
            v2 += __shfl_xor_sync(FULLM, v2, off);
            v3 += __shfl_xor_sync(FULLM, v3, off);
        }
        if (valid && quarter == 0) {
            if (which) { V2[k][0]=v0; V2[k][1]=v1; V2[k][2]=v2; V2[k][3]=v3; }
            else       { V1[k][0]=v0; V1[k][1]=v1; V1[k][2]=v2; V1[k][3]=v3; }
        }
    } else if (w == 9) {
        // Qn: (k9, half) = 18 items on one warp; lanes 18-31 padded (no write)
        const int idx = lane;
        int k9 = idx >> 1; if (k9 > 8) k9 = 8;
        const int half = idx & 1;
        const int cen = jlA(k9, A);
        const int h0 = half * 24;
        float q0=0,q1=0,q2=0,q3=0;
        #pragma unroll
        for (int hi = 0; hi < 24; hi++) {
            int hh = h0 + hi;
            float u = U1[9+k9][hh];
            float cf = f2a[cen][hh] * u * u;
            float4 wv = *(const float4*)&W2s[hh][0];
            q0 = fmaf(cf, wv.x, q0); q1 = fmaf(cf, wv.y, q1);
            q2 = fmaf(cf, wv.z, q2); q3 = fmaf(cf, wv.w, q3);
        }
        q0 += __shfl_xor_sync(FULLM, q0, 1);
        q1 += __shfl_xor_sync(FULLM, q1, 1);
        q2 += __shfl_xor_sync(FULLM, q2, 1);
        q3 += __shfl_xor_sync(FULLM, q3, 1);
        if (idx < 18 && half == 0) {
            Qn[k9][0]=q0; Qn[k9][1]=q1; Qn[k9][2]=q2; Qn[k9][3]=q3;
        }
    } else if (w >= 10 && w <= 12) {
        const int mu = w - 10;
        float q0=0,q1=0,q2=0,q3=0;
        #pragma unroll
        for (int rep = 0; rep < 2; rep++) {
            int hh = lane + rep*32;
            if (hh < HIDDEN) {
                float ud = 0.f;
                #pragma unroll
                for (int k = 0; k < 9; k++)
                    ud = fmaf(wdd[mu][k], U1[k][hh], ud);
                float cf = f2a[A][hh] * ud * ud;
                float4 wv = *(const float4*)&W2s[hh][0];
                q0 = fmaf(cf, wv.x, q0); q1 = fmaf(cf, wv.y, q1);
                q2 = fmaf(cf, wv.z, q2); q3 = fmaf(cf, wv.w, q3);
            }
        }
        #pragma unroll
        for (int off = 16; off > 0; off >>= 1) {
            q0 += __shfl_xor_sync(FULLM, q0, off);
            q1 += __shfl_xor_sync(FULLM, q1, off);
            q2 += __shfl_xor_sync(FULLM, q2, off);
            q3 += __shfl_xor_sync(FULLM, q3, off);
        }
        if (lane == 0) { QA[mu][0]=q0; QA[mu][1]=q1; QA[mu][2]=q2; QA[mu][3]=q3; }
    }
    __syncthreads();

    // -------- Phase D (P6): only warps 0-3 continue; the rest exit --------
    if (w >= 4) return;

    if (tid >= 96 && tid < 96 + NSTATES) {
        int s = tid - 96;
        float acc = 0.f;
        #pragma unroll
        for (int j = 0; j < NATOMS; j++)
            acc = fmaf(pv[j][s], Rr[j], acc);
        Tval[s] = acc;
    }
    if (w < 3) {
        const int mu = w;
        float accA = 0.f;
        if (lane < 8) {
            int s = lane & 3;
            bool second = lane >= 4;
            #pragma unroll
            for (int k = 0; k < 9; k++) {
                float dd = wdd[mu][k], dh = wdh[mu][k];
                accA += second ? fmaf(dd*dd, V2[k][s], dh*V1[k][s])
                               : dd*V1[k][s];
            }
        }
        if (lane < 4)      wpd[mu][A][lane]   = accA;
        else if (lane < 8) wph[mu][A][lane-4] = accA + QA[mu][lane-4];
        __syncwarp();

        #pragma unroll
        for (int base = 0; base < 36; base += 32) {
            int item = base + lane;
            if (item < 36) {
                int k9 = item >> 2, s = item & 3;
                int kk = 9 + k9;
                float dd = wdd[mu][kk], dh = wdh[mu][kk];
                float pd = dd * V1[kk][s];
                float ph = dd*dd*(V2[kk][s] + Qn[k9][s]) + dh*V1[kk][s];
                int at = jlA(k9, A);
                wpd[mu][at][s] = pd;
                wph[mu][at][s] = ph;
            }
        }
        __syncwarp();

        {
            int s = lane & 3, g = lane >> 2;
            float td = 0.f, th = 0.f;
            for (int k = g; k < 9; k += 8) {
                int j = jlA(k, A);
                float ddc = wdd[mu][k], dhc = wdh[mu][k];
                float rdc = rad1k[k]*ddc;
                float rhc = fmaf(rad2k[k], ddc*ddc, rad1k[k]*dhc);
                td = fmaf(pv[j][s], rdc, td);
                th = fmaf(2.f*wpd[mu][j][s], rdc, fmaf(pv[j][s], rhc, th));
                float ddn = wdd[mu][9+k], dhn = wdh[mu][9+k];
                float rdn = rad1k[9+k]*ddn;
                float rhn = fmaf(rad2k[9+k], ddn*ddn, rad1k[9+k]*dhn);
                td = fmaf(pv[A][s], rdn, td);
                th = fmaf(2.f*wpd[mu][A][s], rdn, fmaf(pv[A][s], rhn, th));
            }
            for (int at = g; at < NATOMS; at += 8) {
                td = fmaf(wpd[mu][at][s], Rr[at], td);
                th = fmaf(wph[mu][at][s], Rr[at], th);
            }
            #pragma unroll
            for (int off = 4; off < 32; off <<= 1) {
                td += __shfl_xor_sync(FULLM, td, off);
                th += __shfl_xor_sync(FULLM, th, off);
            }
            if (lane < 4) {
                Bsh[mu][lane] = td;
                Hsh[mu][lane] = th;
            }
        }
    }
    // named barrier over warps 0-3 only (128 threads)
    asm volatile("bar.sync 1, 128;" ::: "memory");

    // -------- Phase E (P7): warp 0 only --------
    if (w != 0) return;
    if (tid < NSTATES) {
        int s = tid;
        float T0 = Tval[0];
        float acc = 0.f;
        #pragma unroll
        for (int mu = 0; mu < 3; mu++) {
            float Bv = Bsh[mu][s], Hv = Hsh[mu][s];
            acc += (s == 0) ? (2.f*Bv*Bv + 2.f*T0*Hv) : Hv;
        }
        atomicAdd(&g_kinCS[c*NSTATES + s], s_mass * acc);   // REDG, no return
        if (A == 0) g_T[c*NSTATES + s] = Tval[s];
    }
    __threadfence();           // publish REDG + g_T before the counter
    __syncwarp();
    int flag = 0;
    if (lane == 0) {
        int old;
        asm volatile("atom.acq_rel.gpu.add.s32 %0, [%1], 1;"
                     : "=r"(old) : "l"(&g_fin) : "memory");
        flag = (old == NBLOCKS - 1);
    }
    flag = __shfl_sync(FULLM, flag, 0);
    if (!flag) return;
    // last block: lane = (config, state); 32 contiguous accumulators
    const int s = tid & 3;
    float kin = -0.5f * g_kinCS[tid];
    float Ts = g_T[tid];
    g_kinCS[tid] = 0.f;                      // reset for next graph replay
    float T0 = __shfl_sync(FULLM, Ts, tid & ~3);
    float psi = (s == 0) ? T0*T0 : Ts;
    float pe  = potA - potLast;              // prefetched at Phase A
    float vib = (kin + psi*pe) / psi;
    float dvv = vib - s_el[s];
    float l = dvv*dvv;
    #pragma unroll
    for (int off = 16; off > 0; off >>= 1)
        l += __shfl_xor_sync(FULLM, l, off);
    if (tid == 0) {
        out[0] = l;
        g_fin = 0;   // reset for next graph replay
    }
}

extern "C" void kernel_launch(void* const* d_in, const int* in_sizes, int n_in,
                              void* d_out, int out_size)
{
    // metadata order: eigen_weight, pot, cart, numatoms, species, massrev,
    //                 atom_index, shifts, W1, B1, W2, Emb, elevel
    const float* pot     = (const float*)d_in[1];
    const float* cart    = (const float*)d_in[2];
    const int*   species = (const int*)  d_in[4];
    const float* massrev = (const float*)d_in[5];
    const float* W1      = (const float*)d_in[8];
    const float* B1      = (const float*)d_in[9];
    const float* W2      = (const float*)d_in[10];
    const float* Emb     = (const float*)d_in[11];
    const float* elevel  = (const float*)d_in[12];

    fused_kernel<<<NBLOCKS, NT>>>(pot, cart, species, massrev,
                                  W1, B1, W2, Emb, elevel, (float*)d_out);
}